// round 13
// baseline (speedup 1.0000x reference)
#include <cuda_runtime.h>
#include <math.h>

#define MPTS 8192
#define KNN  16
#define CINF 128
#define MK   (MPTS*KNN)   // 131072
#define FULLM 0xffffffffu

// ---------------- scratch (device globals; no allocation allowed) ----------------
__device__ float4 g_pos4[MPTS];      // xyz + d2 in .w
__device__ int    g_idx[MK];
__device__ float  g_A2[32*MK];       // mlp1 layer2 (pre-BN), channel-major
__device__ float  g_T0[256*MPTS];    // mlp2 dense   (pre-BN), channel-major [256][8192]
__device__ float  g_T1[256*MPTS];    // gconv-a      (pre-BN)
__device__ float  g_T2[256*MPTS];    // gconv-b      (pre-BN)
__device__ float  g_Y[MPTS*320];     // depthwise output, row-major [8192][320]
__device__ float  g_stats[2048];     // BN scale/shift packs
__device__ float  g_psum[65536];     // BN partial sums   (buffer A; S1 uses 32x2048)
__device__ float  g_psum2[65536];
__device__ float  g_psumB[8192];     // BN partials (buffer B, gconv0 outputs)
__device__ float  g_psum2B[8192];
__device__ float  g_psumC[16384];    // BN partials (buffer C, mlp1b S2 — survives until xconv)
__device__ float  g_psum2C[16384];

#define OFF_S1 0      // 32 scale + 32 shift
#define OFF_S2 64
#define OFF_SC 1152

__device__ __forceinline__ float elu_f(float x){ return x > 0.f ? x : expm1f(x); }

// ---------------- pack pos into float4, with d2 = (x*x + y*y) + z*z in .w ----------------
__global__ void pack_pos_kernel(const float* __restrict__ pos){
    int i = blockIdx.x*blockDim.x + threadIdx.x;
    if (i < MPTS){
        float x = pos[3*i], y = pos[3*i+1], z = pos[3*i+2];
        float d2 = __fadd_rn(__fadd_rn(__fmul_rn(x,x), __fmul_rn(y,y)), __fmul_rn(z,z));
        g_pos4[i] = make_float4(x, y, z, d2);
    }
}

// ---------------- exact kNN + fused mlp1a BN stats ----------------
// One warp per query; lanes 0..15 hold the sorted (dist, idx) list (ascending, (d, idx)
// lexicographic — matches top_k lowest-index-first tie break). After selection, the warp
// already holds its query's 16 neighbors, so it computes mlp1a activations (rel->32, elu)
// for its 16 rows and the block emits S1 partial sums (chunk = blockIdx, 2048 chunks).
__global__ void __launch_bounds__(128) knn_kernel(const float* __restrict__ w1a,
                                                  const float* __restrict__ b1a){
    __shared__ float wA[96], bA[32];
    __shared__ float sbuf[32][65];       // [channel][row within block]
    int t = threadIdx.x;
    if (t < 96) wA[t] = w1a[t];
    if (t < 32) bA[t] = b1a[t];

    int lane = t & 31;
    int warp = t >> 5;
    int q = blockIdx.x*4 + warp;
    float4 qp = g_pos4[q];

    float bd = 3.4e38f;        // this lane's list element (lanes 0..15)
    int   bi = 0x7fffffff;
    float kth = 3.4e38f;

    #pragma unroll 4
    for (int ch = 0; ch < MPTS/32; ch++){
        int j = ch*32 + lane;
        float4 c = g_pos4[j];
        float dot = __fmaf_rn(qp.z, c.z,
                    __fmaf_rn(qp.y, c.y,
                    __fmul_rn(qp.x, c.x)));
        float d = __fsub_rn(__fadd_rn(qp.w, c.w), __fmul_rn(2.0f, dot));
        unsigned ball = __ballot_sync(FULLM, d < kth);
        while (ball){
            int src = __ffs(ball) - 1;       // low->high = ascending j (tie order)
            ball &= ball - 1;
            float cd = __shfl_sync(FULLM, d, src);
            int   cj = ch*32 + src;
            // warp-collective insert into distributed sorted list
            bool before = (lane < 16) && ((cd < bd) || (cd == bd && cj < bi));
            unsigned pm = __ballot_sync(FULLM, before);
            int pos = pm ? (__ffs(pm) - 1) : 16;
            float bd_up = __shfl_up_sync(FULLM, bd, 1);
            int   bi_up = __shfl_up_sync(FULLM, bi, 1);
            if (lane > pos && lane < 16){ bd = bd_up; bi = bi_up; }
            if (lane == pos){ bd = cd; bi = cj; }
            // fresh threshold; prune remaining candidates in this chunk
            kth = __shfl_sync(FULLM, bd, 15);
            ball &= __ballot_sync(FULLM, d < kth);
        }
    }
    if (lane < 16) g_idx[q*16 + lane] = bi;

    // fused mlp1a stats: lane k computes the 32 elu activations for row q*16+k
    if (lane < 16){
        float4 pn = g_pos4[bi];
        float rx = pn.x - qp.x, ry = pn.y - qp.y, rz = pn.z - qp.z;
        #pragma unroll
        for (int c = 0; c < 32; c++){
            float v = bA[c];
            v = fmaf(rx, wA[c], v);
            v = fmaf(ry, wA[32 + c], v);
            v = fmaf(rz, wA[64 + c], v);
            sbuf[c][warp*16 + lane] = elu_f(v);
        }
    }
    __syncthreads();
    if (t < 32){
        float s = 0.f, q2 = 0.f;
        #pragma unroll
        for (int i = 0; i < 64; i++){
            float v = sbuf[t][i];
            s += v; q2 = fmaf(v, v, q2);
        }
        g_psum[t*2048 + blockIdx.x]  = s;
        g_psum2[t*2048 + blockIdx.x] = q2;
    }
}

// ---------------- BN phase 2: fold partials (buffer A) -> scale/shift ----------------
__global__ void __launch_bounds__(32) bn_phase2_kernel(int chunks, int channels, int cols,
                                                       const float* __restrict__ g,
                                                       const float* __restrict__ b,
                                                       int off){
    int c = blockIdx.x;
    float s = 0.f, s2 = 0.f;
    for (int i = threadIdx.x; i < chunks; i += 32){
        s  += g_psum[c*chunks + i];
        s2 += g_psum2[c*chunks + i];
    }
    #pragma unroll
    for (int o = 16; o > 0; o >>= 1){
        s  += __shfl_xor_sync(0xffffffff, s,  o);
        s2 += __shfl_xor_sync(0xffffffff, s2, o);
    }
    if (threadIdx.x == 0){
        float mean = s / (float)cols;
        float var  = s2 / (float)cols - mean*mean;
        float sc = g[c] * rsqrtf(var + 1e-5f);
        g_stats[off + c] = sc;
        g_stats[off + channels + c] = b[c] - mean*sc;
    }
}

// ---------------- merged final BN: S2 (from buffer C) + SC (from buffer A) ----------------
__global__ void __launch_bounds__(32) bn_final_kernel(const float* __restrict__ g1b,
                                                      const float* __restrict__ be1b,
                                                      const float* __restrict__ g2c,
                                                      const float* __restrict__ be2c){
    int b = blockIdx.x;
    const float *ps, *pq, *g, *bb;
    int c, chunks, off, channels; float cols;
    if (b < 32){ c = b;      ps = g_psumC; pq = g_psum2C; chunks = 512; cols = (float)MK;
                 off = OFF_S2; channels = 32;  g = g1b; bb = be1b; }
    else       { c = b - 32; ps = g_psum;  pq = g_psum2;  chunks = 32;  cols = (float)MPTS;
                 off = OFF_SC; channels = 256; g = g2c; bb = be2c; }
    float s = 0.f, s2 = 0.f;
    for (int i = threadIdx.x; i < chunks; i += 32){
        s  += ps[c*chunks + i];
        s2 += pq[c*chunks + i];
    }
    #pragma unroll
    for (int o = 16; o > 0; o >>= 1){
        s  += __shfl_xor_sync(0xffffffff, s,  o);
        s2 += __shfl_xor_sync(0xffffffff, s2, o);
    }
    if (threadIdx.x == 0){
        float mean = s / cols;
        float var  = s2 / cols - mean*mean;
        float sc = g[c] * rsqrtf(var + 1e-5f);
        g_stats[off + c] = sc;
        g_stats[off + channels + c] = bb[c] - mean*sc;
    }
}

// ---------------- mlp1 layer 2: recompute A1, BN, 32 -> 32, elu + S2 partials (buf C) ----------------
__global__ void __launch_bounds__(256) mlp1b_kernel(const float* __restrict__ w1a,
                                                    const float* __restrict__ b1a,
                                                    const float* __restrict__ w1b,
                                                    const float* __restrict__ b1b){
    __shared__ float wa[96], ba[32];
    __shared__ float w[1024];
    __shared__ float buf[32][257];
    __shared__ float pS[32][9], pQ[32][9];
    int t = threadIdx.x;
    if (t < 96) wa[t] = w1a[t];
    if (t < 32) ba[t] = b1a[t];
    for (int i = t; i < 1024; i += 256) w[i] = w1b[i];
    __syncthreads();
    int r = blockIdx.x*256 + t;
    int m = r >> 4;
    int nb = g_idx[r];
    float4 pm = g_pos4[m], pn = g_pos4[nb];
    float rx = pn.x - pm.x, ry = pn.y - pm.y, rz = pn.z - pm.z;
    float hn[32];
    #pragma unroll
    for (int c = 0; c < 32; c++){
        float v = ba[c];
        v = fmaf(rx, wa[c], v);
        v = fmaf(ry, wa[32 + c], v);
        v = fmaf(rz, wa[64 + c], v);
        v = elu_f(v);
        hn[c] = v*g_stats[OFF_S1 + c] + g_stats[OFF_S1 + 32 + c];
    }
    #pragma unroll
    for (int co = 0; co < 32; co++){
        float acc = __ldg(&b1b[co]);
        #pragma unroll
        for (int ci = 0; ci < 32; ci++) acc = fmaf(hn[ci], w[ci*32 + co], acc);
        acc = elu_f(acc);
        g_A2[co*MK + r] = acc;
        buf[co][t] = acc;
    }
    __syncthreads();
    {
        int c = t & 31, g = t >> 5;
        float s = 0.f, q2 = 0.f;
        #pragma unroll
        for (int i = 0; i < 32; i++){
            float v = buf[c][g*32 + i];
            s += v; q2 = fmaf(v, v, q2);
        }
        pS[c][g] = s; pQ[c][g] = q2;
    }
    __syncthreads();
    if (t < 32){
        float s = pS[t][0], q2 = pQ[t][0];
        #pragma unroll
        for (int k = 1; k < 8; k++){ s += pS[t][k]; q2 += pQ[t][k]; }
        g_psumC[t*512 + blockIdx.x]  = s;
        g_psum2C[t*512 + blockIdx.x] = q2;
    }
}

// ---------------- mlp2 dense: rel(48) -> 64-of-256 per block, elu + BN partials (buf A) ----------------
__global__ void __launch_bounds__(256) mlp2a_kernel(const float* __restrict__ w2,
                                                    const float* __restrict__ b2){
    __shared__ float w[48*64];            // only this block's 64 output columns (12KB)
    __shared__ float buf[32][257];
    __shared__ float pS[32][9], pQ[32][9];
    int t = threadIdx.x;
    int s = blockIdx.x >> 5;              // output-channel quarter 0..3
    int chunk = blockIdx.x & 31;
    int m = chunk*256 + t;
    int o0 = s*64;
    for (int idx = t; idx < 48*64; idx += 256){
        int i = idx >> 6, c = idx & 63;
        w[idx] = w2[i*256 + o0 + c];
    }
    __syncthreads();
    float4 pm = g_pos4[m];
    float rel[48];
    #pragma unroll
    for (int k = 0; k < 16; k++){
        int nb = g_idx[m*16 + k];
        float4 pn = g_pos4[nb];
        rel[k*3+0] = pn.x - pm.x;
        rel[k*3+1] = pn.y - pm.y;
        rel[k*3+2] = pn.z - pm.z;
    }
    #pragma unroll 1
    for (int h = 0; h < 2; h++){
        for (int oo = 0; oo < 32; oo++){
            int c = h*32 + oo;            // local channel 0..63
            float acc = __ldg(&b2[o0 + c]);
            #pragma unroll
            for (int i = 0; i < 48; i++) acc = fmaf(rel[i], w[i*64 + c], acc);
            acc = elu_f(acc);
            g_T0[(size_t)(o0 + c)*MPTS + m] = acc;
            buf[oo][t] = acc;
        }
        __syncthreads();
        {
            int c = t & 31, g = t >> 5;
            float sv = 0.f, q2 = 0.f;
            #pragma unroll
            for (int i = 0; i < 32; i++){
                float v = buf[c][g*32 + i];
                sv += v; q2 = fmaf(v, v, q2);
            }
            pS[c][g] = sv; pQ[c][g] = q2;
        }
        __syncthreads();
        if (t < 32){
            float sv = pS[t][0], q2 = pQ[t][0];
            #pragma unroll
            for (int k = 1; k < 8; k++){ sv += pS[t][k]; q2 += pQ[t][k]; }
            g_psum[(o0 + h*32 + t)*32 + chunk]  = sv;
            g_psum2[(o0 + h*32 + t)*32 + chunk] = q2;
        }
        __syncthreads();
    }
}

// ---------------- grouped conv K->K*K with INLINE input BN stats ----------------
// STAGE 0: reads partials A (mlp2a), writes partials B. STAGE 1: reads B, writes A.
template<int STAGE, bool ELU>
__global__ void __launch_bounds__(256) gconv_kernel(const float* __restrict__ wt,
                                                    const float* __restrict__ bias,
                                                    const float* __restrict__ gg,
                                                    const float* __restrict__ gb){
    int cg = blockIdx.x >> 5;                // group, constant per block
    int chunk = blockIdx.x & 31;
    int t = threadIdx.x;
    int m = chunk*256 + t;
    __shared__ float w[256];
    __shared__ float bs[16];
    __shared__ float isc[16], ish[16];       // inline input BN scale/shift
    __shared__ float buf[16][257];
    __shared__ float pS[16][17], pQ[16][17];
    if (t < 16) bs[t] = bias[cg*16 + t];
    w[t] = wt[cg*256 + t];

    const float* inPS = (STAGE == 0) ? g_psum  : g_psumB;
    const float* inPQ = (STAGE == 0) ? g_psum2 : g_psum2B;
    float* outPS = (STAGE == 0) ? g_psumB  : g_psum;
    float* outPQ = (STAGE == 0) ? g_psum2B : g_psum2;

    if (t >= 32 && t < 48){
        int c = cg*16 + (t - 32);
        float s = 0.f, q2 = 0.f;
        #pragma unroll 1
        for (int i = 0; i < 32; i++){ s += inPS[c*32 + i]; q2 += inPQ[c*32 + i]; }
        float mean = s * (1.0f/(float)MPTS);
        float var  = q2 * (1.0f/(float)MPTS) - mean*mean;
        float sc = gg[c] * rsqrtf(var + 1e-5f);
        isc[t - 32] = sc;
        ish[t - 32] = gb[c] - mean*sc;
    }
    __syncthreads();

    const float* in  = (STAGE == 0) ? g_T0 : g_T1;
    float*       out = (STAGE == 0) ? g_T1 : g_T2;

    float x[16];
    #pragma unroll
    for (int l = 0; l < 16; l++){
        int ch = cg*16 + l;
        x[l] = in[(size_t)ch*MPTS + m]*isc[l] + ish[l];
    }
    #pragma unroll
    for (int o = 0; o < 16; o++){
        float acc = bs[o];
        #pragma unroll
        for (int l = 0; l < 16; l++) acc = fmaf(x[l], w[o*16 + l], acc);
        if (ELU) acc = elu_f(acc);
        out[(size_t)(cg*16 + o)*MPTS + m] = acc;
        buf[o][t] = acc;
    }
    __syncthreads();
    {
        int c = t & 15, g = t >> 4;          // 16 groups of 16
        float sv = 0.f, q2 = 0.f;
        #pragma unroll
        for (int i = 0; i < 16; i++){
            float v = buf[c][g*16 + i];
            sv += v; q2 = fmaf(v, v, q2);
        }
        pS[c][g] = sv; pQ[c][g] = q2;
    }
    __syncthreads();
    if (t < 16){
        float sv = pS[t][0], q2 = pQ[t][0];
        #pragma unroll
        for (int k = 1; k < 16; k++){ sv += pS[t][k]; q2 += pQ[t][k]; }
        outPS[(cg*16 + t)*32 + chunk] = sv;
        outPQ[(cg*16 + t)*32 + chunk] = q2;
    }
}

// ---------------- fused per-point: build x_star, apply X-transform, depthwise conv ----------------
__global__ void __launch_bounds__(128) xconv_kernel(const float* __restrict__ xf,
                                                    const float* __restrict__ wcd,
                                                    const float* __restrict__ bcd){
    __shared__ float xs[160*17];
    __shared__ float ts[256];
    __shared__ float xts[160*17];
    __shared__ int   nbr[16];
    int m = blockIdx.x;
    int t = threadIdx.x;
    if (t < 16) nbr[t] = g_idx[m*16 + t];
    #pragma unroll
    for (int e = t; e < 256; e += 128)
        ts[e] = g_T2[(size_t)e*MPTS + m]*g_stats[OFF_SC + e] + g_stats[OFF_SC + 256 + e];
    #pragma unroll
    for (int e = t; e < 512; e += 128){
        int c = e >> 4, k = e & 15;
        xs[c*17 + k] = g_A2[(size_t)c*MK + m*16 + k]*g_stats[OFF_S2 + c] + g_stats[OFF_S2 + 32 + c];
    }
    __syncthreads();
    #pragma unroll
    for (int k = 0; k < 16; k++)
        xs[(32 + t)*17 + k] = __ldg(&xf[(size_t)nbr[k]*CINF + t]);
    __syncthreads();
    // xt[c][j] = sum_k x_star[c][k] * t[k][j]; fixed j per thread -> ts cached in regs
    int j = t & 15, c0 = t >> 4;
    float tr[16];
    #pragma unroll
    for (int k = 0; k < 16; k++) tr[k] = ts[k*16 + j];
    #pragma unroll
    for (int i = 0; i < 20; i++){
        int c = c0 + 8*i;
        float acc = 0.f;
        #pragma unroll
        for (int k = 0; k < 16; k++) acc = fmaf(xs[c*17 + k], tr[k], acc);
        xts[c*17 + j] = acc;
    }
    __syncthreads();
    // y[p] (p = c*2+o) = bcd[p] + sum_l xt[c][l]*wcd[c][o][l]
    #pragma unroll
    for (int i = 0; i < 3; i++){
        int p = t + 128*i;
        if (p < 320){
            int c = p >> 1;
            float acc = __ldg(&bcd[p]);
            #pragma unroll
            for (int l = 0; l < 16; l++)
                acc = fmaf(xts[c*17 + l], __ldg(&wcd[p*16 + l]), acc);
            g_Y[(size_t)m*320 + p] = acc;
        }
    }
}

// ---------------- final linear: [8192,320] @ [320,256] + bl (128x64 tiles) ----------------
__global__ void __launch_bounds__(256) gemm_kernel(const float* __restrict__ wl,
                                                   const float* __restrict__ bl,
                                                   float* __restrict__ out){
    __shared__ float As[16*132];
    __shared__ float Bs[16*64];
    int t  = threadIdx.x;
    int bm = blockIdx.x*128, bn = blockIdx.y*64;
    int tx = t & 15, ty = t >> 4;
    float acc[8][4];
    #pragma unroll
    for (int i = 0; i < 8; i++)
        #pragma unroll
        for (int j = 0; j < 4; j++) acc[i][j] = 0.f;

    for (int k0 = 0; k0 < 320; k0 += 16){
        #pragma unroll
        for (int i = 0; i < 2; i++){
            int item = t + 256*i;
            int r = item >> 2, c4 = item & 3;
            float4 v = *(const float4*)&g_Y[(size_t)(bm + r)*320 + k0 + c4*4];
            As[(c4*4+0)*132 + r] = v.x;
            As[(c4*4+1)*132 + r] = v.y;
            As[(c4*4+2)*132 + r] = v.z;
            As[(c4*4+3)*132 + r] = v.w;
        }
        {
            int r = t >> 4, c = (t & 15)*4;
            float4 v = *(const float4*)&wl[(size_t)(k0 + r)*256 + bn + c];
            *(float4*)&Bs[r*64 + c] = v;
        }
        __syncthreads();
        #pragma unroll
        for (int kk = 0; kk < 16; kk++){
            float a[8], b[4];
            #pragma unroll
            for (int i = 0; i < 8; i++) a[i] = As[kk*132 + ty*8 + i];
            #pragma unroll
            for (int j = 0; j < 4; j++) b[j] = Bs[kk*64 + tx*4 + j];
            #pragma unroll
            for (int i = 0; i < 8; i++)
                #pragma unroll
                for (int j = 0; j < 4; j++) acc[i][j] = fmaf(a[i], b[j], acc[i][j]);
        }
        __syncthreads();
    }
    #pragma unroll
    for (int i = 0; i < 8; i++){
        int row = bm + ty*8 + i;
        #pragma unroll
        for (int j = 0; j < 4; j++){
            int col = bn + tx*4 + j;
            out[(size_t)row*256 + col] = acc[i][j] + __ldg(&bl[col]);
        }
    }
}

// ---------------- launch ----------------
extern "C" void kernel_launch(void* const* d_in, const int* in_sizes, int n_in,
                              void* d_out, int out_size){
    const float* x    = (const float*)d_in[0];
    const float* pos  = (const float*)d_in[1];
    const float* w1a  = (const float*)d_in[2];
    const float* b1a  = (const float*)d_in[3];
    const float* g1a  = (const float*)d_in[4];
    const float* be1a = (const float*)d_in[5];
    const float* w1b  = (const float*)d_in[6];
    const float* b1b  = (const float*)d_in[7];
    const float* g1b  = (const float*)d_in[8];
    const float* be1b = (const float*)d_in[9];
    const float* w2   = (const float*)d_in[10];
    const float* b2   = (const float*)d_in[11];
    const float* g2a  = (const float*)d_in[12];
    const float* be2a = (const float*)d_in[13];
    const float* wc2a = (const float*)d_in[14];
    const float* bc2a = (const float*)d_in[15];
    const float* g2b  = (const float*)d_in[16];
    const float* be2b = (const float*)d_in[17];
    const float* wc2b = (const float*)d_in[18];
    const float* bc2b = (const float*)d_in[19];
    const float* g2c  = (const float*)d_in[20];
    const float* be2c = (const float*)d_in[21];
    const float* wcd  = (const float*)d_in[22];
    const float* bcd  = (const float*)d_in[23];
    const float* wl   = (const float*)d_in[24];
    const float* bl   = (const float*)d_in[25];
    float* out = (float*)d_out;

    pack_pos_kernel<<<32, 256>>>(pos);
    knn_kernel<<<2048, 128>>>(w1a, b1a);
    bn_phase2_kernel<<<32, 32>>>(2048, 32, MK, g1a, be1a, OFF_S1);
    mlp1b_kernel<<<512, 256>>>(w1a, b1a, w1b, b1b);
    mlp2a_kernel<<<128, 256>>>(w2, b2);
    gconv_kernel<0, true><<<512, 256>>>(wc2a, bc2a, g2a, be2a);
    gconv_kernel<1, false><<<512, 256>>>(wc2b, bc2b, g2b, be2b);
    bn_final_kernel<<<288, 32>>>(g1b, be1b, g2c, be2c);
    xconv_kernel<<<MPTS, 128>>>(x, wcd, bcd);
    gemm_kernel<<<dim3(64, 4), 256>>>(wl, bl, out);
}

// round 14
// speedup vs baseline: 1.0693x; 1.0693x over previous
#include <cuda_runtime.h>
#include <math.h>

#define MPTS 8192
#define KNN  16
#define CINF 128
#define MK   (MPTS*KNN)   // 131072
#define FULLM 0xffffffffu

// ---------------- scratch (device globals; no allocation allowed) ----------------
__device__ float4 g_pos4[MPTS];      // xyz + d2 in .w
__device__ int    g_idx[MK];
__device__ float  g_A2[32*MK];       // mlp1 layer2 (pre-BN), channel-major
__device__ float  g_T0[256*MPTS];    // mlp2 dense   (pre-BN), channel-major [256][8192]
__device__ float  g_T1[256*MPTS];    // gconv-a      (pre-BN)
__device__ float  g_T2[256*MPTS];    // gconv-b      (pre-BN)
__device__ float  g_Y[MPTS*320];     // depthwise output, row-major [8192][320]
__device__ float  g_stats[2048];     // BN scale/shift packs
__device__ float  g_psum[16384];     // BN partial sums   (buffer A)
__device__ float  g_psum2[16384];
__device__ float  g_psumB[8192];     // BN partials (buffer B, gconv0 outputs)
__device__ float  g_psum2B[8192];
__device__ float  g_psumC[16384];    // BN partials (buffer C, mlp1b S2 — survives until bn_final)
__device__ float  g_psum2C[16384];

#define OFF_S1 0      // 32 scale + 32 shift
#define OFF_S2 64
#define OFF_SC 1152

__device__ __forceinline__ float elu_f(float x){ return x > 0.f ? x : expm1f(x); }

// ---------------- pack pos into float4, with d2 = (x*x + y*y) + z*z in .w ----------------
__global__ void pack_pos_kernel(const float* __restrict__ pos){
    int i = blockIdx.x*blockDim.x + threadIdx.x;
    if (i < MPTS){
        float x = pos[3*i], y = pos[3*i+1], z = pos[3*i+2];
        float d2 = __fadd_rn(__fadd_rn(__fmul_rn(x,x), __fmul_rn(y,y)), __fmul_rn(z,z));
        g_pos4[i] = make_float4(x, y, z, d2);
    }
}

// ---------------- exact kNN: one warp per query, distributed sorted top-16 ----------------
// Lanes 0..15 hold the sorted (dist, idx) list (ascending, (d, idx) lexicographic — matches
// top_k lowest-index-first tie break). The warp-collective insert is a full lexicographic
// sorted-insert that no-ops on non-qualifying candidates, so admission via a (possibly
// stale) kth threshold is a superset filter — unrolling/pipelining the chunk loop is safe.
__global__ void __launch_bounds__(128) knn_kernel(){
    int lane = threadIdx.x & 31;
    int q = blockIdx.x*4 + (threadIdx.x >> 5);
    float4 qp = g_pos4[q];

    float bd = 3.4e38f;        // this lane's list element (lanes 0..15)
    int   bi = 0x7fffffff;
    float kth = 3.4e38f;

    #pragma unroll 4
    for (int ch = 0; ch < MPTS/32; ch++){
        int j = ch*32 + lane;
        float4 c = g_pos4[j];
        float dot = __fmaf_rn(qp.z, c.z,
                    __fmaf_rn(qp.y, c.y,
                    __fmul_rn(qp.x, c.x)));
        float d = __fsub_rn(__fadd_rn(qp.w, c.w), __fmul_rn(2.0f, dot));
        unsigned ball = __ballot_sync(FULLM, d < kth);
        while (ball){
            int src = __ffs(ball) - 1;       // low->high = ascending j (tie order)
            ball &= ball - 1;
            float cd = __shfl_sync(FULLM, d, src);
            int   cj = ch*32 + src;
            // warp-collective insert into distributed sorted list
            bool before = (lane < 16) && ((cd < bd) || (cd == bd && cj < bi));
            unsigned pm = __ballot_sync(FULLM, before);
            int pos = pm ? (__ffs(pm) - 1) : 16;
            float bd_up = __shfl_up_sync(FULLM, bd, 1);
            int   bi_up = __shfl_up_sync(FULLM, bi, 1);
            if (lane > pos && lane < 16){ bd = bd_up; bi = bi_up; }
            if (lane == pos){ bd = cd; bi = cj; }
            // fresh threshold; prune remaining candidates in this chunk
            kth = __shfl_sync(FULLM, bd, 15);
            ball &= __ballot_sync(FULLM, d < kth);
        }
    }
    if (lane < 16) g_idx[q*16 + lane] = bi;
}

// ---------------- mlp1 layer 1 STATS ONLY: rel(3) -> 32, elu, BN partials ----------------
__global__ void __launch_bounds__(256) mlp1a_kernel(const float* __restrict__ w1a,
                                                    const float* __restrict__ b1a){
    __shared__ float w[96], b[32];
    __shared__ float buf[32][257];
    __shared__ float pS[32][9], pQ[32][9];
    int t = threadIdx.x;
    if (t < 96) w[t] = w1a[t];
    if (t < 32) b[t] = b1a[t];
    __syncthreads();
    int r = blockIdx.x*256 + t;          // 0..131071
    int m = r >> 4;
    int nb = g_idx[r];
    float4 pm = g_pos4[m], pn = g_pos4[nb];
    float rx = pn.x - pm.x, ry = pn.y - pm.y, rz = pn.z - pm.z;
    #pragma unroll
    for (int c = 0; c < 32; c++){
        float v = b[c];
        v = fmaf(rx, w[c], v);
        v = fmaf(ry, w[32 + c], v);
        v = fmaf(rz, w[64 + c], v);
        v = elu_f(v);
        buf[c][t] = v;
    }
    __syncthreads();
    {
        int c = t & 31, g = t >> 5;
        float s = 0.f, q2 = 0.f;
        #pragma unroll
        for (int i = 0; i < 32; i++){
            float v = buf[c][g*32 + i];
            s += v; q2 = fmaf(v, v, q2);
        }
        pS[c][g] = s; pQ[c][g] = q2;
    }
    __syncthreads();
    if (t < 32){
        float s = pS[t][0], q2 = pQ[t][0];
        #pragma unroll
        for (int k = 1; k < 8; k++){ s += pS[t][k]; q2 += pQ[t][k]; }
        g_psum[t*512 + blockIdx.x]  = s;
        g_psum2[t*512 + blockIdx.x] = q2;
    }
}

// ---------------- BN phase 2: fold partials (buffer A) -> scale/shift ----------------
__global__ void __launch_bounds__(32) bn_phase2_kernel(int chunks, int channels, int cols,
                                                       const float* __restrict__ g,
                                                       const float* __restrict__ b,
                                                       int off){
    int c = blockIdx.x;
    float s = 0.f, s2 = 0.f;
    for (int i = threadIdx.x; i < chunks; i += 32){
        s  += g_psum[c*chunks + i];
        s2 += g_psum2[c*chunks + i];
    }
    #pragma unroll
    for (int o = 16; o > 0; o >>= 1){
        s  += __shfl_xor_sync(0xffffffff, s,  o);
        s2 += __shfl_xor_sync(0xffffffff, s2, o);
    }
    if (threadIdx.x == 0){
        float mean = s / (float)cols;
        float var  = s2 / (float)cols - mean*mean;
        float sc = g[c] * rsqrtf(var + 1e-5f);
        g_stats[off + c] = sc;
        g_stats[off + channels + c] = b[c] - mean*sc;
    }
}

// ---------------- merged final BN: S2 (from buffer C) + SC (from buffer A) ----------------
__global__ void __launch_bounds__(32) bn_final_kernel(const float* __restrict__ g1b,
                                                      const float* __restrict__ be1b,
                                                      const float* __restrict__ g2c,
                                                      const float* __restrict__ be2c){
    int b = blockIdx.x;
    const float *ps, *pq, *g, *bb;
    int c, chunks, off, channels; float cols;
    if (b < 32){ c = b;      ps = g_psumC; pq = g_psum2C; chunks = 512; cols = (float)MK;
                 off = OFF_S2; channels = 32;  g = g1b; bb = be1b; }
    else       { c = b - 32; ps = g_psum;  pq = g_psum2;  chunks = 32;  cols = (float)MPTS;
                 off = OFF_SC; channels = 256; g = g2c; bb = be2c; }
    float s = 0.f, s2 = 0.f;
    for (int i = threadIdx.x; i < chunks; i += 32){
        s  += ps[c*chunks + i];
        s2 += pq[c*chunks + i];
    }
    #pragma unroll
    for (int o = 16; o > 0; o >>= 1){
        s  += __shfl_xor_sync(0xffffffff, s,  o);
        s2 += __shfl_xor_sync(0xffffffff, s2, o);
    }
    if (threadIdx.x == 0){
        float mean = s / cols;
        float var  = s2 / cols - mean*mean;
        float sc = g[c] * rsqrtf(var + 1e-5f);
        g_stats[off + c] = sc;
        g_stats[off + channels + c] = bb[c] - mean*sc;
    }
}

// ---------------- mlp1 layer 2: recompute A1, BN, 32 -> 32, elu + S2 partials (buf C) ----------------
__global__ void __launch_bounds__(256) mlp1b_kernel(const float* __restrict__ w1a,
                                                    const float* __restrict__ b1a,
                                                    const float* __restrict__ w1b,
                                                    const float* __restrict__ b1b){
    __shared__ float wa[96], ba[32];
    __shared__ float w[1024];
    __shared__ float buf[32][257];
    __shared__ float pS[32][9], pQ[32][9];
    int t = threadIdx.x;
    if (t < 96) wa[t] = w1a[t];
    if (t < 32) ba[t] = b1a[t];
    for (int i = t; i < 1024; i += 256) w[i] = w1b[i];
    __syncthreads();
    int r = blockIdx.x*256 + t;
    int m = r >> 4;
    int nb = g_idx[r];
    float4 pm = g_pos4[m], pn = g_pos4[nb];
    float rx = pn.x - pm.x, ry = pn.y - pm.y, rz = pn.z - pm.z;
    float hn[32];
    #pragma unroll
    for (int c = 0; c < 32; c++){
        float v = ba[c];
        v = fmaf(rx, wa[c], v);
        v = fmaf(ry, wa[32 + c], v);
        v = fmaf(rz, wa[64 + c], v);
        v = elu_f(v);
        hn[c] = v*g_stats[OFF_S1 + c] + g_stats[OFF_S1 + 32 + c];
    }
    #pragma unroll
    for (int co = 0; co < 32; co++){
        float acc = __ldg(&b1b[co]);
        #pragma unroll
        for (int ci = 0; ci < 32; ci++) acc = fmaf(hn[ci], w[ci*32 + co], acc);
        acc = elu_f(acc);
        g_A2[co*MK + r] = acc;
        buf[co][t] = acc;
    }
    __syncthreads();
    {
        int c = t & 31, g = t >> 5;
        float s = 0.f, q2 = 0.f;
        #pragma unroll
        for (int i = 0; i < 32; i++){
            float v = buf[c][g*32 + i];
            s += v; q2 = fmaf(v, v, q2);
        }
        pS[c][g] = s; pQ[c][g] = q2;
    }
    __syncthreads();
    if (t < 32){
        float s = pS[t][0], q2 = pQ[t][0];
        #pragma unroll
        for (int k = 1; k < 8; k++){ s += pS[t][k]; q2 += pQ[t][k]; }
        g_psumC[t*512 + blockIdx.x]  = s;
        g_psum2C[t*512 + blockIdx.x] = q2;
    }
}

// ---------------- mlp2 dense: rel(48) -> 64-of-256 per block, elu + BN partials (buf A) ----------------
__global__ void __launch_bounds__(256) mlp2a_kernel(const float* __restrict__ w2,
                                                    const float* __restrict__ b2){
    __shared__ float w[48*64];            // only this block's 64 output columns (12KB)
    __shared__ float buf[32][257];
    __shared__ float pS[32][9], pQ[32][9];
    int t = threadIdx.x;
    int s = blockIdx.x >> 5;              // output-channel quarter 0..3
    int chunk = blockIdx.x & 31;
    int m = chunk*256 + t;
    int o0 = s*64;
    for (int idx = t; idx < 48*64; idx += 256){
        int i = idx >> 6, c = idx & 63;
        w[idx] = w2[i*256 + o0 + c];
    }
    __syncthreads();
    float4 pm = g_pos4[m];
    float rel[48];
    #pragma unroll
    for (int k = 0; k < 16; k++){
        int nb = g_idx[m*16 + k];
        float4 pn = g_pos4[nb];
        rel[k*3+0] = pn.x - pm.x;
        rel[k*3+1] = pn.y - pm.y;
        rel[k*3+2] = pn.z - pm.z;
    }
    #pragma unroll 1
    for (int h = 0; h < 2; h++){
        for (int oo = 0; oo < 32; oo++){
            int c = h*32 + oo;            // local channel 0..63
            float acc = __ldg(&b2[o0 + c]);
            #pragma unroll
            for (int i = 0; i < 48; i++) acc = fmaf(rel[i], w[i*64 + c], acc);
            acc = elu_f(acc);
            g_T0[(size_t)(o0 + c)*MPTS + m] = acc;
            buf[oo][t] = acc;
        }
        __syncthreads();
        {
            int c = t & 31, g = t >> 5;
            float sv = 0.f, q2 = 0.f;
            #pragma unroll
            for (int i = 0; i < 32; i++){
                float v = buf[c][g*32 + i];
                sv += v; q2 = fmaf(v, v, q2);
            }
            pS[c][g] = sv; pQ[c][g] = q2;
        }
        __syncthreads();
        if (t < 32){
            float sv = pS[t][0], q2 = pQ[t][0];
            #pragma unroll
            for (int k = 1; k < 8; k++){ sv += pS[t][k]; q2 += pQ[t][k]; }
            g_psum[(o0 + h*32 + t)*32 + chunk]  = sv;
            g_psum2[(o0 + h*32 + t)*32 + chunk] = q2;
        }
        __syncthreads();
    }
}

// ---------------- grouped conv K->K*K with INLINE input BN stats ----------------
// STAGE 0: reads partials A (mlp2a), writes partials B. STAGE 1: reads B, writes A.
template<int STAGE, bool ELU>
__global__ void __launch_bounds__(256) gconv_kernel(const float* __restrict__ wt,
                                                    const float* __restrict__ bias,
                                                    const float* __restrict__ gg,
                                                    const float* __restrict__ gb){
    int cg = blockIdx.x >> 5;                // group, constant per block
    int chunk = blockIdx.x & 31;
    int t = threadIdx.x;
    int m = chunk*256 + t;
    __shared__ float w[256];
    __shared__ float bs[16];
    __shared__ float isc[16], ish[16];       // inline input BN scale/shift
    __shared__ float buf[16][257];
    __shared__ float pS[16][17], pQ[16][17];
    if (t < 16) bs[t] = bias[cg*16 + t];
    w[t] = wt[cg*256 + t];

    const float* inPS = (STAGE == 0) ? g_psum  : g_psumB;
    const float* inPQ = (STAGE == 0) ? g_psum2 : g_psum2B;
    float* outPS = (STAGE == 0) ? g_psumB  : g_psum;
    float* outPQ = (STAGE == 0) ? g_psum2B : g_psum2;

    if (t >= 32 && t < 48){
        int c = cg*16 + (t - 32);
        float s = 0.f, q2 = 0.f;
        #pragma unroll 1
        for (int i = 0; i < 32; i++){ s += inPS[c*32 + i]; q2 += inPQ[c*32 + i]; }
        float mean = s * (1.0f/(float)MPTS);
        float var  = q2 * (1.0f/(float)MPTS) - mean*mean;
        float sc = gg[c] * rsqrtf(var + 1e-5f);
        isc[t - 32] = sc;
        ish[t - 32] = gb[c] - mean*sc;
    }
    __syncthreads();

    const float* in  = (STAGE == 0) ? g_T0 : g_T1;
    float*       out = (STAGE == 0) ? g_T1 : g_T2;

    float x[16];
    #pragma unroll
    for (int l = 0; l < 16; l++){
        int ch = cg*16 + l;
        x[l] = in[(size_t)ch*MPTS + m]*isc[l] + ish[l];
    }
    #pragma unroll
    for (int o = 0; o < 16; o++){
        float acc = bs[o];
        #pragma unroll
        for (int l = 0; l < 16; l++) acc = fmaf(x[l], w[o*16 + l], acc);
        if (ELU) acc = elu_f(acc);
        out[(size_t)(cg*16 + o)*MPTS + m] = acc;
        buf[o][t] = acc;
    }
    __syncthreads();
    {
        int c = t & 15, g = t >> 4;          // 16 groups of 16
        float sv = 0.f, q2 = 0.f;
        #pragma unroll
        for (int i = 0; i < 16; i++){
            float v = buf[c][g*16 + i];
            sv += v; q2 = fmaf(v, v, q2);
        }
        pS[c][g] = sv; pQ[c][g] = q2;
    }
    __syncthreads();
    if (t < 16){
        float sv = pS[t][0], q2 = pQ[t][0];
        #pragma unroll
        for (int k = 1; k < 16; k++){ sv += pS[t][k]; q2 += pQ[t][k]; }
        outPS[(cg*16 + t)*32 + chunk] = sv;
        outPQ[(cg*16 + t)*32 + chunk] = q2;
    }
}

// ---------------- fused per-point: build x_star, apply X-transform, depthwise conv ----------------
__global__ void __launch_bounds__(128) xconv_kernel(const float* __restrict__ xf,
                                                    const float* __restrict__ wcd,
                                                    const float* __restrict__ bcd){
    __shared__ float xs[160*17];
    __shared__ float ts[256];
    __shared__ float xts[160*17];
    __shared__ int   nbr[16];
    int m = blockIdx.x;
    int t = threadIdx.x;
    if (t < 16) nbr[t] = g_idx[m*16 + t];
    #pragma unroll
    for (int e = t; e < 256; e += 128)
        ts[e] = g_T2[(size_t)e*MPTS + m]*g_stats[OFF_SC + e] + g_stats[OFF_SC + 256 + e];
    #pragma unroll
    for (int e = t; e < 512; e += 128){
        int c = e >> 4, k = e & 15;
        xs[c*17 + k] = g_A2[(size_t)c*MK + m*16 + k]*g_stats[OFF_S2 + c] + g_stats[OFF_S2 + 32 + c];
    }
    __syncthreads();
    #pragma unroll
    for (int k = 0; k < 16; k++)
        xs[(32 + t)*17 + k] = __ldg(&xf[(size_t)nbr[k]*CINF + t]);
    __syncthreads();
    // xt[c][j] = sum_k x_star[c][k] * t[k][j]; fixed j per thread -> ts cached in regs
    int j = t & 15, c0 = t >> 4;
    float tr[16];
    #pragma unroll
    for (int k = 0; k < 16; k++) tr[k] = ts[k*16 + j];
    #pragma unroll
    for (int i = 0; i < 20; i++){
        int c = c0 + 8*i;
        float acc = 0.f;
        #pragma unroll
        for (int k = 0; k < 16; k++) acc = fmaf(xs[c*17 + k], tr[k], acc);
        xts[c*17 + j] = acc;
    }
    __syncthreads();
    // y[p] (p = c*2+o) = bcd[p] + sum_l xt[c][l]*wcd[c][o][l]
    #pragma unroll
    for (int i = 0; i < 3; i++){
        int p = t + 128*i;
        if (p < 320){
            int c = p >> 1;
            float acc = __ldg(&bcd[p]);
            #pragma unroll
            for (int l = 0; l < 16; l++)
                acc = fmaf(xts[c*17 + l], __ldg(&wcd[p*16 + l]), acc);
            g_Y[(size_t)m*320 + p] = acc;
        }
    }
}

// ---------------- final linear: [8192,320] @ [320,256] + bl (128x64 tiles) ----------------
__global__ void __launch_bounds__(256) gemm_kernel(const float* __restrict__ wl,
                                                   const float* __restrict__ bl,
                                                   float* __restrict__ out){
    __shared__ float As[16*132];
    __shared__ float Bs[16*64];
    int t  = threadIdx.x;
    int bm = blockIdx.x*128, bn = blockIdx.y*64;
    int tx = t & 15, ty = t >> 4;
    float acc[8][4];
    #pragma unroll
    for (int i = 0; i < 8; i++)
        #pragma unroll
        for (int j = 0; j < 4; j++) acc[i][j] = 0.f;

    for (int k0 = 0; k0 < 320; k0 += 16){
        #pragma unroll
        for (int i = 0; i < 2; i++){
            int item = t + 256*i;
            int r = item >> 2, c4 = item & 3;
            float4 v = *(const float4*)&g_Y[(size_t)(bm + r)*320 + k0 + c4*4];
            As[(c4*4+0)*132 + r] = v.x;
            As[(c4*4+1)*132 + r] = v.y;
            As[(c4*4+2)*132 + r] = v.z;
            As[(c4*4+3)*132 + r] = v.w;
        }
        {
            int r = t >> 4, c = (t & 15)*4;
            float4 v = *(const float4*)&wl[(size_t)(k0 + r)*256 + bn + c];
            *(float4*)&Bs[r*64 + c] = v;
        }
        __syncthreads();
        #pragma unroll
        for (int kk = 0; kk < 16; kk++){
            float a[8], b[4];
            #pragma unroll
            for (int i = 0; i < 8; i++) a[i] = As[kk*132 + ty*8 + i];
            #pragma unroll
            for (int j = 0; j < 4; j++) b[j] = Bs[kk*64 + tx*4 + j];
            #pragma unroll
            for (int i = 0; i < 8; i++)
                #pragma unroll
                for (int j = 0; j < 4; j++) acc[i][j] = fmaf(a[i], b[j], acc[i][j]);
        }
        __syncthreads();
    }
    #pragma unroll
    for (int i = 0; i < 8; i++){
        int row = bm + ty*8 + i;
        #pragma unroll
        for (int j = 0; j < 4; j++){
            int col = bn + tx*4 + j;
            out[(size_t)row*256 + col] = acc[i][j] + __ldg(&bl[col]);
        }
    }
}

// ---------------- launch ----------------
extern "C" void kernel_launch(void* const* d_in, const int* in_sizes, int n_in,
                              void* d_out, int out_size){
    const float* x    = (const float*)d_in[0];
    const float* pos  = (const float*)d_in[1];
    const float* w1a  = (const float*)d_in[2];
    const float* b1a  = (const float*)d_in[3];
    const float* g1a  = (const float*)d_in[4];
    const float* be1a = (const float*)d_in[5];
    const float* w1b  = (const float*)d_in[6];
    const float* b1b  = (const float*)d_in[7];
    const float* g1b  = (const float*)d_in[8];
    const float* be1b = (const float*)d_in[9];
    const float* w2   = (const float*)d_in[10];
    const float* b2   = (const float*)d_in[11];
    const float* g2a  = (const float*)d_in[12];
    const float* be2a = (const float*)d_in[13];
    const float* wc2a = (const float*)d_in[14];
    const float* bc2a = (const float*)d_in[15];
    const float* g2b  = (const float*)d_in[16];
    const float* be2b = (const float*)d_in[17];
    const float* wc2b = (const float*)d_in[18];
    const float* bc2b = (const float*)d_in[19];
    const float* g2c  = (const float*)d_in[20];
    const float* be2c = (const float*)d_in[21];
    const float* wcd  = (const float*)d_in[22];
    const float* bcd  = (const float*)d_in[23];
    const float* wl   = (const float*)d_in[24];
    const float* bl   = (const float*)d_in[25];
    float* out = (float*)d_out;

    pack_pos_kernel<<<32, 256>>>(pos);
    knn_kernel<<<2048, 128>>>();

    mlp1a_kernel<<<512, 256>>>(w1a, b1a);
    bn_phase2_kernel<<<32, 32>>>(512, 32, MK, g1a, be1a, OFF_S1);
    mlp1b_kernel<<<512, 256>>>(w1a, b1a, w1b, b1b);
    mlp2a_kernel<<<128, 256>>>(w2, b2);
    gconv_kernel<0, true><<<512, 256>>>(wc2a, bc2a, g2a, be2a);
    gconv_kernel<1, false><<<512, 256>>>(wc2b, bc2b, g2b, be2b);
    bn_final_kernel<<<288, 32>>>(g1b, be1b, g2c, be2c);
    xconv_kernel<<<MPTS, 128>>>(x, wcd, bcd);
    gemm_kernel<<<dim3(64, 4), 256>>>(wl, bl, out);
}

// round 15
// speedup vs baseline: 1.3095x; 1.2247x over previous
#include <cuda_runtime.h>
#include <math.h>

#define MPTS 8192
#define KNN  16
#define CINF 128
#define MK   (MPTS*KNN)   // 131072
#define FULLM 0xffffffffu

// ---------------- scratch (device globals; no allocation allowed) ----------------
__device__ float4 g_pos4[MPTS];      // xyz + d2 in .w
__device__ int    g_idx[MK];
__device__ float  g_A2[32*MK];       // mlp1 layer2 (pre-BN), channel-major
__device__ float  g_T0[256*MPTS];    // mlp2 dense   (pre-BN), channel-major [256][8192]
__device__ float  g_T1[256*MPTS];    // gconv-a      (pre-BN)
__device__ float  g_T2[256*MPTS];    // gconv-b      (pre-BN)
__device__ float  g_Y[MPTS*320];     // depthwise output, row-major [8192][320]
__device__ __align__(16) float g_stats[2048];   // BN scale/shift packs
__device__ float  g_psum[16384];     // BN partial sums   (buffer A)
__device__ float  g_psum2[16384];
__device__ float  g_psumB[8192];     // BN partials (buffer B, gconv0 outputs)
__device__ float  g_psum2B[8192];
__device__ float  g_psumC[16384];    // BN partials (buffer C, mlp1b S2 — survives until bn_final)
__device__ float  g_psum2C[16384];

#define OFF_S1 0      // 32 scale + 32 shift
#define OFF_S2 64
#define OFF_SC 1152

__device__ __forceinline__ float elu_f(float x){ return x > 0.f ? x : expm1f(x); }

// ---------------- pack pos into float4, with d2 = (x*x + y*y) + z*z in .w ----------------
__global__ void pack_pos_kernel(const float* __restrict__ pos){
    int i = blockIdx.x*blockDim.x + threadIdx.x;
    if (i < MPTS){
        float x = pos[3*i], y = pos[3*i+1], z = pos[3*i+2];
        float d2 = __fadd_rn(__fadd_rn(__fmul_rn(x,x), __fmul_rn(y,y)), __fmul_rn(z,z));
        g_pos4[i] = make_float4(x, y, z, d2);
    }
}

// ---------------- exact kNN: one warp per query, distributed sorted top-16 ----------------
__global__ void __launch_bounds__(128) knn_kernel(){
    int lane = threadIdx.x & 31;
    int q = blockIdx.x*4 + (threadIdx.x >> 5);
    float4 qp = g_pos4[q];

    float bd = 3.4e38f;        // this lane's list element (lanes 0..15)
    int   bi = 0x7fffffff;
    float kth = 3.4e38f;

    #pragma unroll 4
    for (int ch = 0; ch < MPTS/32; ch++){
        int j = ch*32 + lane;
        float4 c = g_pos4[j];
        float dot = __fmaf_rn(qp.z, c.z,
                    __fmaf_rn(qp.y, c.y,
                    __fmul_rn(qp.x, c.x)));
        float d = __fsub_rn(__fadd_rn(qp.w, c.w), __fmul_rn(2.0f, dot));
        unsigned ball = __ballot_sync(FULLM, d < kth);
        while (ball){
            int src = __ffs(ball) - 1;       // low->high = ascending j (tie order)
            ball &= ball - 1;
            float cd = __shfl_sync(FULLM, d, src);
            int   cj = ch*32 + src;
            bool before = (lane < 16) && ((cd < bd) || (cd == bd && cj < bi));
            unsigned pm = __ballot_sync(FULLM, before);
            int pos = pm ? (__ffs(pm) - 1) : 16;
            float bd_up = __shfl_up_sync(FULLM, bd, 1);
            int   bi_up = __shfl_up_sync(FULLM, bi, 1);
            if (lane > pos && lane < 16){ bd = bd_up; bi = bi_up; }
            if (lane == pos){ bd = cd; bi = cj; }
            kth = __shfl_sync(FULLM, bd, 15);
            ball &= __ballot_sync(FULLM, d < kth);
        }
    }
    if (lane < 16) g_idx[q*16 + lane] = bi;
}

// ---------------- mlp1 layer 1 STATS ONLY: rel(3) -> 32, elu, BN partials ----------------
__global__ void __launch_bounds__(256) mlp1a_kernel(const float* __restrict__ w1a,
                                                    const float* __restrict__ b1a){
    __shared__ __align__(16) float w[96], b[32];
    __shared__ float buf[32][257];
    __shared__ float pS[32][9], pQ[32][9];
    int t = threadIdx.x;
    if (t < 96) w[t] = w1a[t];
    if (t < 32) b[t] = b1a[t];
    __syncthreads();
    int r = blockIdx.x*256 + t;          // 0..131071
    int m = r >> 4;
    int nb = g_idx[r];
    float4 pm = g_pos4[m], pn = g_pos4[nb];
    float rx = pn.x - pm.x, ry = pn.y - pm.y, rz = pn.z - pm.z;
    #pragma unroll
    for (int c4 = 0; c4 < 32; c4 += 4){
        float4 b4 = *(const float4*)&b[c4];
        float4 w0 = *(const float4*)&w[c4];
        float4 w1 = *(const float4*)&w[32 + c4];
        float4 w2 = *(const float4*)&w[64 + c4];
        float v0 = fmaf(rz, w2.x, fmaf(ry, w1.x, fmaf(rx, w0.x, b4.x)));
        float v1 = fmaf(rz, w2.y, fmaf(ry, w1.y, fmaf(rx, w0.y, b4.y)));
        float v2 = fmaf(rz, w2.z, fmaf(ry, w1.z, fmaf(rx, w0.z, b4.z)));
        float v3 = fmaf(rz, w2.w, fmaf(ry, w1.w, fmaf(rx, w0.w, b4.w)));
        buf[c4+0][t] = elu_f(v0);
        buf[c4+1][t] = elu_f(v1);
        buf[c4+2][t] = elu_f(v2);
        buf[c4+3][t] = elu_f(v3);
    }
    __syncthreads();
    {
        int c = t & 31, g = t >> 5;
        float s = 0.f, q2 = 0.f;
        #pragma unroll
        for (int i = 0; i < 32; i++){
            float v = buf[c][g*32 + i];
            s += v; q2 = fmaf(v, v, q2);
        }
        pS[c][g] = s; pQ[c][g] = q2;
    }
    __syncthreads();
    if (t < 32){
        float s = pS[t][0], q2 = pQ[t][0];
        #pragma unroll
        for (int k = 1; k < 8; k++){ s += pS[t][k]; q2 += pQ[t][k]; }
        g_psum[t*512 + blockIdx.x]  = s;
        g_psum2[t*512 + blockIdx.x] = q2;
    }
}

// ---------------- BN phase 2: fold partials (buffer A) -> scale/shift ----------------
__global__ void __launch_bounds__(32) bn_phase2_kernel(int chunks, int channels, int cols,
                                                       const float* __restrict__ g,
                                                       const float* __restrict__ b,
                                                       int off){
    int c = blockIdx.x;
    float s = 0.f, s2 = 0.f;
    for (int i = threadIdx.x; i < chunks; i += 32){
        s  += g_psum[c*chunks + i];
        s2 += g_psum2[c*chunks + i];
    }
    #pragma unroll
    for (int o = 16; o > 0; o >>= 1){
        s  += __shfl_xor_sync(0xffffffff, s,  o);
        s2 += __shfl_xor_sync(0xffffffff, s2, o);
    }
    if (threadIdx.x == 0){
        float mean = s / (float)cols;
        float var  = s2 / (float)cols - mean*mean;
        float sc = g[c] * rsqrtf(var + 1e-5f);
        g_stats[off + c] = sc;
        g_stats[off + channels + c] = b[c] - mean*sc;
    }
}

// ---------------- merged final BN: S2 (from buffer C) + SC (from buffer A) ----------------
__global__ void __launch_bounds__(32) bn_final_kernel(const float* __restrict__ g1b,
                                                      const float* __restrict__ be1b,
                                                      const float* __restrict__ g2c,
                                                      const float* __restrict__ be2c){
    int b = blockIdx.x;
    const float *ps, *pq, *g, *bb;
    int c, chunks, off, channels; float cols;
    if (b < 32){ c = b;      ps = g_psumC; pq = g_psum2C; chunks = 512; cols = (float)MK;
                 off = OFF_S2; channels = 32;  g = g1b; bb = be1b; }
    else       { c = b - 32; ps = g_psum;  pq = g_psum2;  chunks = 32;  cols = (float)MPTS;
                 off = OFF_SC; channels = 256; g = g2c; bb = be2c; }
    float s = 0.f, s2 = 0.f;
    for (int i = threadIdx.x; i < chunks; i += 32){
        s  += ps[c*chunks + i];
        s2 += pq[c*chunks + i];
    }
    #pragma unroll
    for (int o = 16; o > 0; o >>= 1){
        s  += __shfl_xor_sync(0xffffffff, s,  o);
        s2 += __shfl_xor_sync(0xffffffff, s2, o);
    }
    if (threadIdx.x == 0){
        float mean = s / cols;
        float var  = s2 / cols - mean*mean;
        float sc = g[c] * rsqrtf(var + 1e-5f);
        g_stats[off + c] = sc;
        g_stats[off + channels + c] = bb[c] - mean*sc;
    }
}

// ---------------- mlp1 layer 2: recompute A1, BN, 32 -> 32, elu + S2 partials (buf C) ----------------
__global__ void __launch_bounds__(256) mlp1b_kernel(const float* __restrict__ w1a,
                                                    const float* __restrict__ b1a,
                                                    const float* __restrict__ w1b,
                                                    const float* __restrict__ b1b){
    __shared__ __align__(16) float wa[96], ba[32];
    __shared__ __align__(16) float w[1024];
    __shared__ float buf[32][257];
    __shared__ float pS[32][9], pQ[32][9];
    int t = threadIdx.x;
    if (t < 96) wa[t] = w1a[t];
    if (t < 32) ba[t] = b1a[t];
    for (int i = t; i < 1024; i += 256) w[i] = w1b[i];
    __syncthreads();
    int r = blockIdx.x*256 + t;
    int m = r >> 4;
    int nb = g_idx[r];
    float4 pm = g_pos4[m], pn = g_pos4[nb];
    float rx = pn.x - pm.x, ry = pn.y - pm.y, rz = pn.z - pm.z;
    float hn[32];
    #pragma unroll
    for (int c4 = 0; c4 < 32; c4 += 4){
        float4 b4 = *(const float4*)&ba[c4];
        float4 w0 = *(const float4*)&wa[c4];
        float4 w1 = *(const float4*)&wa[32 + c4];
        float4 w2 = *(const float4*)&wa[64 + c4];
        float4 sc4 = *(const float4*)&g_stats[OFF_S1 + c4];
        float4 sh4 = *(const float4*)&g_stats[OFF_S1 + 32 + c4];
        hn[c4+0] = elu_f(fmaf(rz, w2.x, fmaf(ry, w1.x, fmaf(rx, w0.x, b4.x))))*sc4.x + sh4.x;
        hn[c4+1] = elu_f(fmaf(rz, w2.y, fmaf(ry, w1.y, fmaf(rx, w0.y, b4.y))))*sc4.y + sh4.y;
        hn[c4+2] = elu_f(fmaf(rz, w2.z, fmaf(ry, w1.z, fmaf(rx, w0.z, b4.z))))*sc4.z + sh4.z;
        hn[c4+3] = elu_f(fmaf(rz, w2.w, fmaf(ry, w1.w, fmaf(rx, w0.w, b4.w))))*sc4.w + sh4.w;
    }
    #pragma unroll
    for (int co4 = 0; co4 < 32; co4 += 4){
        float4 b4 = __ldg((const float4*)&b1b[co4]);
        float a0 = b4.x, a1 = b4.y, a2 = b4.z, a3 = b4.w;
        #pragma unroll
        for (int ci = 0; ci < 32; ci++){
            float h = hn[ci];
            float4 wv = *(const float4*)&w[ci*32 + co4];
            a0 = fmaf(h, wv.x, a0);
            a1 = fmaf(h, wv.y, a1);
            a2 = fmaf(h, wv.z, a2);
            a3 = fmaf(h, wv.w, a3);
        }
        a0 = elu_f(a0); a1 = elu_f(a1); a2 = elu_f(a2); a3 = elu_f(a3);
        g_A2[(co4+0)*MK + r] = a0; buf[co4+0][t] = a0;
        g_A2[(co4+1)*MK + r] = a1; buf[co4+1][t] = a1;
        g_A2[(co4+2)*MK + r] = a2; buf[co4+2][t] = a2;
        g_A2[(co4+3)*MK + r] = a3; buf[co4+3][t] = a3;
    }
    __syncthreads();
    {
        int c = t & 31, g = t >> 5;
        float s = 0.f, q2 = 0.f;
        #pragma unroll
        for (int i = 0; i < 32; i++){
            float v = buf[c][g*32 + i];
            s += v; q2 = fmaf(v, v, q2);
        }
        pS[c][g] = s; pQ[c][g] = q2;
    }
    __syncthreads();
    if (t < 32){
        float s = pS[t][0], q2 = pQ[t][0];
        #pragma unroll
        for (int k = 1; k < 8; k++){ s += pS[t][k]; q2 += pQ[t][k]; }
        g_psumC[t*512 + blockIdx.x]  = s;
        g_psum2C[t*512 + blockIdx.x] = q2;
    }
}

// ---------------- mlp2 dense: rel(48) -> 64-of-256 per block, elu + BN partials (buf A) ----------------
__global__ void __launch_bounds__(256) mlp2a_kernel(const float* __restrict__ w2,
                                                    const float* __restrict__ b2){
    __shared__ __align__(16) float w[48*64];   // this block's 64 output columns (12KB)
    __shared__ float buf[32][257];
    __shared__ float pS[32][9], pQ[32][9];
    int t = threadIdx.x;
    int s = blockIdx.x >> 5;              // output-channel quarter 0..3
    int chunk = blockIdx.x & 31;
    int m = chunk*256 + t;
    int o0 = s*64;
    for (int idx = t; idx < 48*64; idx += 256){
        int i = idx >> 6, c = idx & 63;
        w[idx] = w2[i*256 + o0 + c];
    }
    __syncthreads();
    float4 pm = g_pos4[m];
    float rel[48];
    #pragma unroll
    for (int k = 0; k < 16; k++){
        int nb = g_idx[m*16 + k];
        float4 pn = g_pos4[nb];
        rel[k*3+0] = pn.x - pm.x;
        rel[k*3+1] = pn.y - pm.y;
        rel[k*3+2] = pn.z - pm.z;
    }
    #pragma unroll 1
    for (int h = 0; h < 2; h++){
        #pragma unroll 1
        for (int c4 = 0; c4 < 32; c4 += 4){
            int c = h*32 + c4;            // local channel
            float4 b4 = __ldg((const float4*)&b2[o0 + c]);
            float a0 = b4.x, a1 = b4.y, a2 = b4.z, a3 = b4.w;
            #pragma unroll
            for (int i = 0; i < 48; i++){
                float rv = rel[i];
                float4 wv = *(const float4*)&w[i*64 + c];
                a0 = fmaf(rv, wv.x, a0);
                a1 = fmaf(rv, wv.y, a1);
                a2 = fmaf(rv, wv.z, a2);
                a3 = fmaf(rv, wv.w, a3);
            }
            a0 = elu_f(a0); a1 = elu_f(a1); a2 = elu_f(a2); a3 = elu_f(a3);
            g_T0[(size_t)(o0 + c + 0)*MPTS + m] = a0; buf[c4+0][t] = a0;
            g_T0[(size_t)(o0 + c + 1)*MPTS + m] = a1; buf[c4+1][t] = a1;
            g_T0[(size_t)(o0 + c + 2)*MPTS + m] = a2; buf[c4+2][t] = a2;
            g_T0[(size_t)(o0 + c + 3)*MPTS + m] = a3; buf[c4+3][t] = a3;
        }
        __syncthreads();
        {
            int c = t & 31, g = t >> 5;
            float sv = 0.f, q2 = 0.f;
            #pragma unroll
            for (int i = 0; i < 32; i++){
                float v = buf[c][g*32 + i];
                sv += v; q2 = fmaf(v, v, q2);
            }
            pS[c][g] = sv; pQ[c][g] = q2;
        }
        __syncthreads();
        if (t < 32){
            float sv = pS[t][0], q2 = pQ[t][0];
            #pragma unroll
            for (int k = 1; k < 8; k++){ sv += pS[t][k]; q2 += pQ[t][k]; }
            g_psum[(o0 + h*32 + t)*32 + chunk]  = sv;
            g_psum2[(o0 + h*32 + t)*32 + chunk] = q2;
        }
        __syncthreads();
    }
}

// ---------------- grouped conv K->K*K with INLINE input BN stats ----------------
// STAGE 0: reads partials A (mlp2a), writes partials B. STAGE 1: reads B, writes A.
template<int STAGE, bool ELU>
__global__ void __launch_bounds__(256) gconv_kernel(const float* __restrict__ wt,
                                                    const float* __restrict__ bias,
                                                    const float* __restrict__ gg,
                                                    const float* __restrict__ gb){
    int cg = blockIdx.x >> 5;                // group, constant per block
    int chunk = blockIdx.x & 31;
    int t = threadIdx.x;
    int m = chunk*256 + t;
    __shared__ __align__(16) float w[256];
    __shared__ float bs[16];
    __shared__ float isc[16], ish[16];       // inline input BN scale/shift
    __shared__ float buf[16][257];
    __shared__ float pS[16][17], pQ[16][17];
    if (t < 16) bs[t] = bias[cg*16 + t];
    w[t] = wt[cg*256 + t];

    const float* inPS = (STAGE == 0) ? g_psum  : g_psumB;
    const float* inPQ = (STAGE == 0) ? g_psum2 : g_psum2B;
    float* outPS = (STAGE == 0) ? g_psumB  : g_psum;
    float* outPQ = (STAGE == 0) ? g_psum2B : g_psum2;

    if (t >= 32 && t < 48){
        int c = cg*16 + (t - 32);
        float s = 0.f, q2 = 0.f;
        #pragma unroll 1
        for (int i = 0; i < 32; i++){ s += inPS[c*32 + i]; q2 += inPQ[c*32 + i]; }
        float mean = s * (1.0f/(float)MPTS);
        float var  = q2 * (1.0f/(float)MPTS) - mean*mean;
        float sc = gg[c] * rsqrtf(var + 1e-5f);
        isc[t - 32] = sc;
        ish[t - 32] = gb[c] - mean*sc;
    }
    __syncthreads();

    const float* in  = (STAGE == 0) ? g_T0 : g_T1;
    float*       out = (STAGE == 0) ? g_T1 : g_T2;

    float x[16];
    #pragma unroll
    for (int l = 0; l < 16; l++){
        int ch = cg*16 + l;
        x[l] = in[(size_t)ch*MPTS + m]*isc[l] + ish[l];
    }
    #pragma unroll
    for (int o = 0; o < 16; o++){
        float acc = bs[o];
        #pragma unroll
        for (int l4 = 0; l4 < 16; l4 += 4){
            float4 wv = *(const float4*)&w[o*16 + l4];
            acc = fmaf(x[l4+0], wv.x, acc);
            acc = fmaf(x[l4+1], wv.y, acc);
            acc = fmaf(x[l4+2], wv.z, acc);
            acc = fmaf(x[l4+3], wv.w, acc);
        }
        if (ELU) acc = elu_f(acc);
        out[(size_t)(cg*16 + o)*MPTS + m] = acc;
        buf[o][t] = acc;
    }
    __syncthreads();
    {
        int c = t & 15, g = t >> 4;          // 16 groups of 16
        float sv = 0.f, q2 = 0.f;
        #pragma unroll
        for (int i = 0; i < 16; i++){
            float v = buf[c][g*16 + i];
            sv += v; q2 = fmaf(v, v, q2);
        }
        pS[c][g] = sv; pQ[c][g] = q2;
    }
    __syncthreads();
    if (t < 16){
        float sv = pS[t][0], q2 = pQ[t][0];
        #pragma unroll
        for (int k = 1; k < 16; k++){ sv += pS[t][k]; q2 += pQ[t][k]; }
        outPS[(cg*16 + t)*32 + chunk] = sv;
        outPQ[(cg*16 + t)*32 + chunk] = q2;
    }
}

// ---------------- fused per-point: build x_star, apply X-transform, depthwise conv ----------------
// row pitch 20 floats (80B) keeps rows 16B-aligned for float4 LDS.
__global__ void __launch_bounds__(128) xconv_kernel(const float* __restrict__ xf,
                                                    const float* __restrict__ wcd,
                                                    const float* __restrict__ bcd){
    __shared__ __align__(16) float xs[160*20];
    __shared__ float ts[256];
    __shared__ __align__(16) float xts[160*20];
    __shared__ int   nbr[16];
    int m = blockIdx.x;
    int t = threadIdx.x;
    if (t < 16) nbr[t] = g_idx[m*16 + t];
    #pragma unroll
    for (int e = t; e < 256; e += 128)
        ts[e] = g_T2[(size_t)e*MPTS + m]*g_stats[OFF_SC + e] + g_stats[OFF_SC + 256 + e];
    #pragma unroll
    for (int e = t; e < 512; e += 128){
        int c = e >> 4, k = e & 15;
        xs[c*20 + k] = g_A2[(size_t)c*MK + m*16 + k]*g_stats[OFF_S2 + c] + g_stats[OFF_S2 + 32 + c];
    }
    __syncthreads();
    #pragma unroll
    for (int k = 0; k < 16; k++)
        xs[(32 + t)*20 + k] = __ldg(&xf[(size_t)nbr[k]*CINF + t]);
    __syncthreads();
    // xt[c][j] = sum_k x_star[c][k] * t[k][j]; fixed j per thread -> ts cached in regs
    int j = t & 15, c0 = t >> 4;
    float tr[16];
    #pragma unroll
    for (int k = 0; k < 16; k++) tr[k] = ts[k*16 + j];
    #pragma unroll
    for (int i = 0; i < 20; i++){
        int c = c0 + 8*i;
        float acc = 0.f;
        #pragma unroll
        for (int k4 = 0; k4 < 16; k4 += 4){
            float4 xv = *(const float4*)&xs[c*20 + k4];
            acc = fmaf(xv.x, tr[k4+0], acc);
            acc = fmaf(xv.y, tr[k4+1], acc);
            acc = fmaf(xv.z, tr[k4+2], acc);
            acc = fmaf(xv.w, tr[k4+3], acc);
        }
        xts[c*20 + j] = acc;
    }
    __syncthreads();
    // y[p] (p = c*2+o) = bcd[p] + sum_l xt[c][l]*wcd[c][o][l]
    #pragma unroll
    for (int i = 0; i < 3; i++){
        int p = t + 128*i;
        if (p < 320){
            int c = p >> 1;
            float acc = __ldg(&bcd[p]);
            #pragma unroll
            for (int l4 = 0; l4 < 16; l4 += 4){
                float4 xv = *(const float4*)&xts[c*20 + l4];
                float4 wv = __ldg((const float4*)&wcd[p*16 + l4]);
                acc = fmaf(xv.x, wv.x, acc);
                acc = fmaf(xv.y, wv.y, acc);
                acc = fmaf(xv.z, wv.z, acc);
                acc = fmaf(xv.w, wv.w, acc);
            }
            g_Y[(size_t)m*320 + p] = acc;
        }
    }
}

// ---------------- final linear: [8192,320] @ [320,256] + bl (128x64 tiles) ----------------
__global__ void __launch_bounds__(256) gemm_kernel(const float* __restrict__ wl,
                                                   const float* __restrict__ bl,
                                                   float* __restrict__ out){
    __shared__ float As[16*132];
    __shared__ __align__(16) float Bs[16*64];
    int t  = threadIdx.x;
    int bm = blockIdx.x*128, bn = blockIdx.y*64;
    int tx = t & 15, ty = t >> 4;
    float acc[8][4];
    #pragma unroll
    for (int i = 0; i < 8; i++)
        #pragma unroll
        for (int j = 0; j < 4; j++) acc[i][j] = 0.f;

    for (int k0 = 0; k0 < 320; k0 += 16){
        #pragma unroll
        for (int i = 0; i < 2; i++){
            int item = t + 256*i;
            int r = item >> 2, c4 = item & 3;
            float4 v = *(const float4*)&g_Y[(size_t)(bm + r)*320 + k0 + c4*4];
            As[(c4*4+0)*132 + r] = v.x;
            As[(c4*4+1)*132 + r] = v.y;
            As[(c4*4+2)*132 + r] = v.z;
            As[(c4*4+3)*132 + r] = v.w;
        }
        {
            int r = t >> 4, c = (t & 15)*4;
            float4 v = *(const float4*)&wl[(size_t)(k0 + r)*256 + bn + c];
            *(float4*)&Bs[r*64 + c] = v;
        }
        __syncthreads();
        #pragma unroll
        for (int kk = 0; kk < 16; kk++){
            float a[8], b[4];
            #pragma unroll
            for (int i = 0; i < 8; i++) a[i] = As[kk*132 + ty*8 + i];
            #pragma unroll
            for (int j = 0; j < 4; j++) b[j] = Bs[kk*64 + tx*4 + j];
            #pragma unroll
            for (int i = 0; i < 8; i++)
                #pragma unroll
                for (int j = 0; j < 4; j++) acc[i][j] = fmaf(a[i], b[j], acc[i][j]);
        }
        __syncthreads();
    }
    #pragma unroll
    for (int i = 0; i < 8; i++){
        int row = bm + ty*8 + i;
        #pragma unroll
        for (int j = 0; j < 4; j++){
            int col = bn + tx*4 + j;
            out[(size_t)row*256 + col] = acc[i][j] + __ldg(&bl[col]);
        }
    }
}

// ---------------- launch ----------------
extern "C" void kernel_launch(void* const* d_in, const int* in_sizes, int n_in,
                              void* d_out, int out_size){
    const float* x    = (const float*)d_in[0];
    const float* pos  = (const float*)d_in[1];
    const float* w1a  = (const float*)d_in[2];
    const float* b1a  = (const float*)d_in[3];
    const float* g1a  = (const float*)d_in[4];
    const float* be1a = (const float*)d_in[5];
    const float* w1b  = (const float*)d_in[6];
    const float* b1b  = (const float*)d_in[7];
    const float* g1b  = (const float*)d_in[8];
    const float* be1b = (const float*)d_in[9];
    const float* w2   = (const float*)d_in[10];
    const float* b2   = (const float*)d_in[11];
    const float* g2a  = (const float*)d_in[12];
    const float* be2a = (const float*)d_in[13];
    const float* wc2a = (const float*)d_in[14];
    const float* bc2a = (const float*)d_in[15];
    const float* g2b  = (const float*)d_in[16];
    const float* be2b = (const float*)d_in[17];
    const float* wc2b = (const float*)d_in[18];
    const float* bc2b = (const float*)d_in[19];
    const float* g2c  = (const float*)d_in[20];
    const float* be2c = (const float*)d_in[21];
    const float* wcd  = (const float*)d_in[22];
    const float* bcd  = (const float*)d_in[23];
    const float* wl   = (const float*)d_in[24];
    const float* bl   = (const float*)d_in[25];
    float* out = (float*)d_out;

    pack_pos_kernel<<<32, 256>>>(pos);
    knn_kernel<<<2048, 128>>>();

    mlp1a_kernel<<<512, 256>>>(w1a, b1a);
    bn_phase2_kernel<<<32, 32>>>(512, 32, MK, g1a, be1a, OFF_S1);
    mlp1b_kernel<<<512, 256>>>(w1a, b1a, w1b, b1b);
    mlp2a_kernel<<<128, 256>>>(w2, b2);
    gconv_kernel<0, true><<<512, 256>>>(wc2a, bc2a, g2a, be2a);
    gconv_kernel<1, false><<<512, 256>>>(wc2b, bc2b, g2b, be2b);
    bn_final_kernel<<<288, 32>>>(g1b, be1b, g2c, be2c);
    xconv_kernel<<<MPTS, 128>>>(x, wcd, bcd);
    gemm_kernel<<<dim3(64, 4), 256>>>(wl, bl, out);
}

// round 17
// speedup vs baseline: 1.4398x; 1.0995x over previous
#include <cuda_runtime.h>
#include <math.h>

#define MPTS 8192
#define KNN  16
#define CINF 128
#define MK   (MPTS*KNN)   // 131072
#define FULLM 0xffffffffu

// ---------------- scratch (device globals; no allocation allowed) ----------------
__device__ float4 g_pos4[MPTS];      // xyz + d2 in .w
__device__ int    g_idx[MK];
__device__ float  g_A2[32*MK];       // mlp1 layer2 (pre-BN), channel-major
__device__ float  g_T0[256*MPTS];    // mlp2 dense   (pre-BN), channel-major [256][8192]
__device__ float  g_T1[256*MPTS];    // gconv-a      (pre-BN)
__device__ float  g_T2[256*MPTS];    // gconv-b      (pre-BN)
__device__ float  g_Y[MPTS*320];     // depthwise output, row-major [8192][320]
__device__ __align__(16) float g_stats[2048];   // BN scale/shift packs
// chain A partials (S1: 32x512, then reused never again)
__device__ float  g_psum[16384];
__device__ float  g_psum2[16384];
// chain A partials (S2 from mlp1b; consumed at bn_final)
__device__ float  g_psumC[16384];
__device__ float  g_psum2C[16384];
// chain B partials: D (mlp2a out / gconv1 out) and B (gconv0 out) — disjoint from chain A
__device__ float  g_psumD[8192];
__device__ float  g_psum2D[8192];
__device__ float  g_psumB[8192];
__device__ float  g_psum2B[8192];

#define OFF_S1 0      // 32 scale + 32 shift
#define OFF_S2 64
#define OFF_SC 1152

__device__ __forceinline__ float elu_f(float x){ return x > 0.f ? x : expm1f(x); }

// ---------------- pack pos into float4, with d2 = (x*x + y*y) + z*z in .w ----------------
__global__ void pack_pos_kernel(const float* __restrict__ pos){
    int i = blockIdx.x*blockDim.x + threadIdx.x;
    if (i < MPTS){
        float x = pos[3*i], y = pos[3*i+1], z = pos[3*i+2];
        float d2 = __fadd_rn(__fadd_rn(__fmul_rn(x,x), __fmul_rn(y,y)), __fmul_rn(z,z));
        g_pos4[i] = make_float4(x, y, z, d2);
    }
}

// ---------------- exact kNN: one warp per query, distributed sorted top-16 ----------------
__global__ void __launch_bounds__(128) knn_kernel(){
    int lane = threadIdx.x & 31;
    int q = blockIdx.x*4 + (threadIdx.x >> 5);
    float4 qp = g_pos4[q];

    float bd = 3.4e38f;        // this lane's list element (lanes 0..15)
    int   bi = 0x7fffffff;
    float kth = 3.4e38f;

    #pragma unroll 4
    for (int ch = 0; ch < MPTS/32; ch++){
        int j = ch*32 + lane;
        float4 c = g_pos4[j];
        float dot = __fmaf_rn(qp.z, c.z,
                    __fmaf_rn(qp.y, c.y,
                    __fmul_rn(qp.x, c.x)));
        float d = __fsub_rn(__fadd_rn(qp.w, c.w), __fmul_rn(2.0f, dot));
        unsigned ball = __ballot_sync(FULLM, d < kth);
        while (ball){
            int src = __ffs(ball) - 1;       // low->high = ascending j (tie order)
            ball &= ball - 1;
            float cd = __shfl_sync(FULLM, d, src);
            int   cj = ch*32 + src;
            bool before = (lane < 16) && ((cd < bd) || (cd == bd && cj < bi));
            unsigned pm = __ballot_sync(FULLM, before);
            int pos = pm ? (__ffs(pm) - 1) : 16;
            float bd_up = __shfl_up_sync(FULLM, bd, 1);
            int   bi_up = __shfl_up_sync(FULLM, bi, 1);
            if (lane > pos && lane < 16){ bd = bd_up; bi = bi_up; }
            if (lane == pos){ bd = cd; bi = cj; }
            kth = __shfl_sync(FULLM, bd, 15);
            ball &= __ballot_sync(FULLM, d < kth);
        }
    }
    if (lane < 16) g_idx[q*16 + lane] = bi;
}

// ---------------- mlp1 layer 1 STATS ONLY: rel(3) -> 32, elu, BN partials (psum) ----------------
__global__ void __launch_bounds__(256) mlp1a_kernel(const float* __restrict__ w1a,
                                                    const float* __restrict__ b1a){
    __shared__ __align__(16) float w[96], b[32];
    __shared__ float buf[32][257];
    __shared__ float pS[32][9], pQ[32][9];
    int t = threadIdx.x;
    if (t < 96) w[t] = w1a[t];
    if (t < 32) b[t] = b1a[t];
    __syncthreads();
    int r = blockIdx.x*256 + t;          // 0..131071
    int m = r >> 4;
    int nb = g_idx[r];
    float4 pm = g_pos4[m], pn = g_pos4[nb];
    float rx = pn.x - pm.x, ry = pn.y - pm.y, rz = pn.z - pm.z;
    #pragma unroll
    for (int c4 = 0; c4 < 32; c4 += 4){
        float4 b4 = *(const float4*)&b[c4];
        float4 w0 = *(const float4*)&w[c4];
        float4 w1 = *(const float4*)&w[32 + c4];
        float4 w2 = *(const float4*)&w[64 + c4];
        float v0 = fmaf(rz, w2.x, fmaf(ry, w1.x, fmaf(rx, w0.x, b4.x)));
        float v1 = fmaf(rz, w2.y, fmaf(ry, w1.y, fmaf(rx, w0.y, b4.y)));
        float v2 = fmaf(rz, w2.z, fmaf(ry, w1.z, fmaf(rx, w0.z, b4.z)));
        float v3 = fmaf(rz, w2.w, fmaf(ry, w1.w, fmaf(rx, w0.w, b4.w)));
        buf[c4+0][t] = elu_f(v0);
        buf[c4+1][t] = elu_f(v1);
        buf[c4+2][t] = elu_f(v2);
        buf[c4+3][t] = elu_f(v3);
    }
    __syncthreads();
    {
        int c = t & 31, g = t >> 5;
        float s = 0.f, q2 = 0.f;
        #pragma unroll
        for (int i = 0; i < 32; i++){
            float v = buf[c][g*32 + i];
            s += v; q2 = fmaf(v, v, q2);
        }
        pS[c][g] = s; pQ[c][g] = q2;
    }
    __syncthreads();
    if (t < 32){
        float s = pS[t][0], q2 = pQ[t][0];
        #pragma unroll
        for (int k = 1; k < 8; k++){ s += pS[t][k]; q2 += pQ[t][k]; }
        g_psum[t*512 + blockIdx.x]  = s;
        g_psum2[t*512 + blockIdx.x] = q2;
    }
}

// ---------------- BN phase 2: fold partials (psum) -> scale/shift ----------------
__global__ void __launch_bounds__(32) bn_phase2_kernel(int chunks, int channels, int cols,
                                                       const float* __restrict__ g,
                                                       const float* __restrict__ b,
                                                       int off){
    int c = blockIdx.x;
    float s = 0.f, s2 = 0.f;
    for (int i = threadIdx.x; i < chunks; i += 32){
        s  += g_psum[c*chunks + i];
        s2 += g_psum2[c*chunks + i];
    }
    #pragma unroll
    for (int o = 16; o > 0; o >>= 1){
        s  += __shfl_xor_sync(0xffffffff, s,  o);
        s2 += __shfl_xor_sync(0xffffffff, s2, o);
    }
    if (threadIdx.x == 0){
        float mean = s / (float)cols;
        float var  = s2 / (float)cols - mean*mean;
        float sc = g[c] * rsqrtf(var + 1e-5f);
        g_stats[off + c] = sc;
        g_stats[off + channels + c] = b[c] - mean*sc;
    }
}

// ---------------- merged final BN: S2 (from psumC) + SC (from psumD) ----------------
__global__ void __launch_bounds__(32) bn_final_kernel(const float* __restrict__ g1b,
                                                      const float* __restrict__ be1b,
                                                      const float* __restrict__ g2c,
                                                      const float* __restrict__ be2c){
    int b = blockIdx.x;
    const float *ps, *pq, *g, *bb;
    int c, chunks, off, channels; float cols;
    if (b < 32){ c = b;      ps = g_psumC; pq = g_psum2C; chunks = 512; cols = (float)MK;
                 off = OFF_S2; channels = 32;  g = g1b; bb = be1b; }
    else       { c = b - 32; ps = g_psumD; pq = g_psum2D; chunks = 32;  cols = (float)MPTS;
                 off = OFF_SC; channels = 256; g = g2c; bb = be2c; }
    float s = 0.f, s2 = 0.f;
    for (int i = threadIdx.x; i < chunks; i += 32){
        s  += ps[c*chunks + i];
        s2 += pq[c*chunks + i];
    }
    #pragma unroll
    for (int o = 16; o > 0; o >>= 1){
        s  += __shfl_xor_sync(0xffffffff, s,  o);
        s2 += __shfl_xor_sync(0xffffffff, s2, o);
    }
    if (threadIdx.x == 0){
        float mean = s / cols;
        float var  = s2 / cols - mean*mean;
        float sc = g[c] * rsqrtf(var + 1e-5f);
        g_stats[off + c] = sc;
        g_stats[off + channels + c] = bb[c] - mean*sc;
    }
}

// ---------------- mlp1 layer 2: recompute A1, BN, 32 -> 32, elu + S2 partials (psumC) ----------------
__global__ void __launch_bounds__(256) mlp1b_kernel(const float* __restrict__ w1a,
                                                    const float* __restrict__ b1a,
                                                    const float* __restrict__ w1b,
                                                    const float* __restrict__ b1b){
    __shared__ __align__(16) float wa[96], ba[32];
    __shared__ __align__(16) float w[1024];
    __shared__ float buf[32][257];
    __shared__ float pS[32][9], pQ[32][9];
    int t = threadIdx.x;
    if (t < 96) wa[t] = w1a[t];
    if (t < 32) ba[t] = b1a[t];
    for (int i = t; i < 1024; i += 256) w[i] = w1b[i];
    __syncthreads();
    int r = blockIdx.x*256 + t;
    int m = r >> 4;
    int nb = g_idx[r];
    float4 pm = g_pos4[m], pn = g_pos4[nb];
    float rx = pn.x - pm.x, ry = pn.y - pm.y, rz = pn.z - pm.z;
    float hn[32];
    #pragma unroll
    for (int c4 = 0; c4 < 32; c4 += 4){
        float4 b4 = *(const float4*)&ba[c4];
        float4 w0 = *(const float4*)&wa[c4];
        float4 w1 = *(const float4*)&wa[32 + c4];
        float4 w2 = *(const float4*)&wa[64 + c4];
        float4 sc4 = *(const float4*)&g_stats[OFF_S1 + c4];
        float4 sh4 = *(const float4*)&g_stats[OFF_S1 + 32 + c4];
        hn[c4+0] = elu_f(fmaf(rz, w2.x, fmaf(ry, w1.x, fmaf(rx, w0.x, b4.x))))*sc4.x + sh4.x;
        hn[c4+1] = elu_f(fmaf(rz, w2.y, fmaf(ry, w1.y, fmaf(rx, w0.y, b4.y))))*sc4.y + sh4.y;
        hn[c4+2] = elu_f(fmaf(rz, w2.z, fmaf(ry, w1.z, fmaf(rx, w0.z, b4.z))))*sc4.z + sh4.z;
        hn[c4+3] = elu_f(fmaf(rz, w2.w, fmaf(ry, w1.w, fmaf(rx, w0.w, b4.w))))*sc4.w + sh4.w;
    }
    #pragma unroll
    for (int co4 = 0; co4 < 32; co4 += 4){
        float4 b4 = __ldg((const float4*)&b1b[co4]);
        float a0 = b4.x, a1 = b4.y, a2 = b4.z, a3 = b4.w;
        #pragma unroll
        for (int ci = 0; ci < 32; ci++){
            float h = hn[ci];
            float4 wv = *(const float4*)&w[ci*32 + co4];
            a0 = fmaf(h, wv.x, a0);
            a1 = fmaf(h, wv.y, a1);
            a2 = fmaf(h, wv.z, a2);
            a3 = fmaf(h, wv.w, a3);
        }
        a0 = elu_f(a0); a1 = elu_f(a1); a2 = elu_f(a2); a3 = elu_f(a3);
        g_A2[(co4+0)*MK + r] = a0; buf[co4+0][t] = a0;
        g_A2[(co4+1)*MK + r] = a1; buf[co4+1][t] = a1;
        g_A2[(co4+2)*MK + r] = a2; buf[co4+2][t] = a2;
        g_A2[(co4+3)*MK + r] = a3; buf[co4+3][t] = a3;
    }
    __syncthreads();
    {
        int c = t & 31, g = t >> 5;
        float s = 0.f, q2 = 0.f;
        #pragma unroll
        for (int i = 0; i < 32; i++){
            float v = buf[c][g*32 + i];
            s += v; q2 = fmaf(v, v, q2);
        }
        pS[c][g] = s; pQ[c][g] = q2;
    }
    __syncthreads();
    if (t < 32){
        float s = pS[t][0], q2 = pQ[t][0];
        #pragma unroll
        for (int k = 1; k < 8; k++){ s += pS[t][k]; q2 += pQ[t][k]; }
        g_psumC[t*512 + blockIdx.x]  = s;
        g_psum2C[t*512 + blockIdx.x] = q2;
    }
}

// ---------------- mlp2 dense: rel(48) -> 64-of-256 per block, elu + BN partials (psumD) ----------------
__global__ void __launch_bounds__(256) mlp2a_kernel(const float* __restrict__ w2,
                                                    const float* __restrict__ b2){
    __shared__ __align__(16) float w[48*64];   // this block's 64 output columns (12KB)
    __shared__ float buf[32][257];
    __shared__ float pS[32][9], pQ[32][9];
    int t = threadIdx.x;
    int s = blockIdx.x >> 5;              // output-channel quarter 0..3
    int chunk = blockIdx.x & 31;
    int m = chunk*256 + t;
    int o0 = s*64;
    for (int idx = t; idx < 48*64; idx += 256){
        int i = idx >> 6, c = idx & 63;
        w[idx] = w2[i*256 + o0 + c];
    }
    __syncthreads();
    float4 pm = g_pos4[m];
    float rel[48];
    #pragma unroll
    for (int k = 0; k < 16; k++){
        int nb = g_idx[m*16 + k];
        float4 pn = g_pos4[nb];
        rel[k*3+0] = pn.x - pm.x;
        rel[k*3+1] = pn.y - pm.y;
        rel[k*3+2] = pn.z - pm.z;
    }
    #pragma unroll 1
    for (int h = 0; h < 2; h++){
        #pragma unroll 1
        for (int c4 = 0; c4 < 32; c4 += 4){
            int c = h*32 + c4;            // local channel
            float4 b4 = __ldg((const float4*)&b2[o0 + c]);
            float a0 = b4.x, a1 = b4.y, a2 = b4.z, a3 = b4.w;
            #pragma unroll
            for (int i = 0; i < 48; i++){
                float rv = rel[i];
                float4 wv = *(const float4*)&w[i*64 + c];
                a0 = fmaf(rv, wv.x, a0);
                a1 = fmaf(rv, wv.y, a1);
                a2 = fmaf(rv, wv.z, a2);
                a3 = fmaf(rv, wv.w, a3);
            }
            a0 = elu_f(a0); a1 = elu_f(a1); a2 = elu_f(a2); a3 = elu_f(a3);
            g_T0[(size_t)(o0 + c + 0)*MPTS + m] = a0; buf[c4+0][t] = a0;
            g_T0[(size_t)(o0 + c + 1)*MPTS + m] = a1; buf[c4+1][t] = a1;
            g_T0[(size_t)(o0 + c + 2)*MPTS + m] = a2; buf[c4+2][t] = a2;
            g_T0[(size_t)(o0 + c + 3)*MPTS + m] = a3; buf[c4+3][t] = a3;
        }
        __syncthreads();
        {
            int c = t & 31, g = t >> 5;
            float sv = 0.f, q2 = 0.f;
            #pragma unroll
            for (int i = 0; i < 32; i++){
                float v = buf[c][g*32 + i];
                sv += v; q2 = fmaf(v, v, q2);
            }
            pS[c][g] = sv; pQ[c][g] = q2;
        }
        __syncthreads();
        if (t < 32){
            float sv = pS[t][0], q2 = pQ[t][0];
            #pragma unroll
            for (int k = 1; k < 8; k++){ sv += pS[t][k]; q2 += pQ[t][k]; }
            g_psumD[(o0 + h*32 + t)*32 + chunk]  = sv;
            g_psum2D[(o0 + h*32 + t)*32 + chunk] = q2;
        }
        __syncthreads();
    }
}

// ---------------- grouped conv K->K*K with INLINE input BN stats ----------------
// STAGE 0: reads partials D (mlp2a), writes partials B. STAGE 1: reads B, writes D.
template<int STAGE, bool ELU>
__global__ void __launch_bounds__(256) gconv_kernel(const float* __restrict__ wt,
                                                    const float* __restrict__ bias,
                                                    const float* __restrict__ gg,
                                                    const float* __restrict__ gb){
    int cg = blockIdx.x >> 5;                // group, constant per block
    int chunk = blockIdx.x & 31;
    int t = threadIdx.x;
    int m = chunk*256 + t;
    __shared__ __align__(16) float w[256];
    __shared__ float bs[16];
    __shared__ float isc[16], ish[16];       // inline input BN scale/shift
    __shared__ float buf[16][257];
    __shared__ float pS[16][17], pQ[16][17];
    if (t < 16) bs[t] = bias[cg*16 + t];
    w[t] = wt[cg*256 + t];

    const float* inPS = (STAGE == 0) ? g_psumD  : g_psumB;
    const float* inPQ = (STAGE == 0) ? g_psum2D : g_psum2B;
    float* outPS = (STAGE == 0) ? g_psumB  : g_psumD;
    float* outPQ = (STAGE == 0) ? g_psum2B : g_psum2D;

    if (t >= 32 && t < 48){
        int c = cg*16 + (t - 32);
        float s = 0.f, q2 = 0.f;
        #pragma unroll 1
        for (int i = 0; i < 32; i++){ s += inPS[c*32 + i]; q2 += inPQ[c*32 + i]; }
        float mean = s * (1.0f/(float)MPTS);
        float var  = q2 * (1.0f/(float)MPTS) - mean*mean;
        float sc = gg[c] * rsqrtf(var + 1e-5f);
        isc[t - 32] = sc;
        ish[t - 32] = gb[c] - mean*sc;
    }
    __syncthreads();

    const float* in  = (STAGE == 0) ? g_T0 : g_T1;
    float*       out = (STAGE == 0) ? g_T1 : g_T2;

    float x[16];
    #pragma unroll
    for (int l = 0; l < 16; l++){
        int ch = cg*16 + l;
        x[l] = in[(size_t)ch*MPTS + m]*isc[l] + ish[l];
    }
    #pragma unroll
    for (int o = 0; o < 16; o++){
        float acc = bs[o];
        #pragma unroll
        for (int l4 = 0; l4 < 16; l4 += 4){
            float4 wv = *(const float4*)&w[o*16 + l4];
            acc = fmaf(x[l4+0], wv.x, acc);
            acc = fmaf(x[l4+1], wv.y, acc);
            acc = fmaf(x[l4+2], wv.z, acc);
            acc = fmaf(x[l4+3], wv.w, acc);
        }
        if (ELU) acc = elu_f(acc);
        out[(size_t)(cg*16 + o)*MPTS + m] = acc;
        buf[o][t] = acc;
    }
    __syncthreads();
    {
        int c = t & 15, g = t >> 4;          // 16 groups of 16
        float sv = 0.f, q2 = 0.f;
        #pragma unroll
        for (int i = 0; i < 16; i++){
            float v = buf[c][g*16 + i];
            sv += v; q2 = fmaf(v, v, q2);
        }
        pS[c][g] = sv; pQ[c][g] = q2;
    }
    __syncthreads();
    if (t < 16){
        float sv = pS[t][0], q2 = pQ[t][0];
        #pragma unroll
        for (int k = 1; k < 16; k++){ sv += pS[t][k]; q2 += pQ[t][k]; }
        outPS[(cg*16 + t)*32 + chunk] = sv;
        outPQ[(cg*16 + t)*32 + chunk] = q2;
    }
}

// ---------------- fused per-point: build x_star, apply X-transform, depthwise conv ----------------
// row pitch 20 floats (80B) keeps rows 16B-aligned for float4 LDS.
__global__ void __launch_bounds__(128) xconv_kernel(const float* __restrict__ xf,
                                                    const float* __restrict__ wcd,
                                                    const float* __restrict__ bcd){
    __shared__ __align__(16) float xs[160*20];
    __shared__ float ts[256];
    __shared__ __align__(16) float xts[160*20];
    __shared__ int   nbr[16];
    int m = blockIdx.x;
    int t = threadIdx.x;
    if (t < 16) nbr[t] = g_idx[m*16 + t];
    #pragma unroll
    for (int e = t; e < 256; e += 128)
        ts[e] = g_T2[(size_t)e*MPTS + m]*g_stats[OFF_SC + e] + g_stats[OFF_SC + 256 + e];
    #pragma unroll
    for (int e = t; e < 512; e += 128){
        int c = e >> 4, k = e & 15;
        xs[c*20 + k] = g_A2[(size_t)c*MK + m*16 + k]*g_stats[OFF_S2 + c] + g_stats[OFF_S2 + 32 + c];
    }
    __syncthreads();
    #pragma unroll
    for (int k = 0; k < 16; k++)
        xs[(32 + t)*20 + k] = __ldg(&xf[(size_t)nbr[k]*CINF + t]);
    __syncthreads();
    // xt[c][j] = sum_k x_star[c][k] * t[k][j]; fixed j per thread -> ts cached in regs
    int j = t & 15, c0 = t >> 4;
    float tr[16];
    #pragma unroll
    for (int k = 0; k < 16; k++) tr[k] = ts[k*16 + j];
    #pragma unroll
    for (int i = 0; i < 20; i++){
        int c = c0 + 8*i;
        float acc = 0.f;
        #pragma unroll
        for (int k4 = 0; k4 < 16; k4 += 4){
            float4 xv = *(const float4*)&xs[c*20 + k4];
            acc = fmaf(xv.x, tr[k4+0], acc);
            acc = fmaf(xv.y, tr[k4+1], acc);
            acc = fmaf(xv.z, tr[k4+2], acc);
            acc = fmaf(xv.w, tr[k4+3], acc);
        }
        xts[c*20 + j] = acc;
    }
    __syncthreads();
    // y[p] (p = c*2+o) = bcd[p] + sum_l xt[c][l]*wcd[c][o][l]
    #pragma unroll
    for (int i = 0; i < 3; i++){
        int p = t + 128*i;
        if (p < 320){
            int c = p >> 1;
            float acc = __ldg(&bcd[p]);
            #pragma unroll
            for (int l4 = 0; l4 < 16; l4 += 4){
                float4 xv = *(const float4*)&xts[c*20 + l4];
                float4 wv = __ldg((const float4*)&wcd[p*16 + l4]);
                acc = fmaf(xv.x, wv.x, acc);
                acc = fmaf(xv.y, wv.y, acc);
                acc = fmaf(xv.z, wv.z, acc);
                acc = fmaf(xv.w, wv.w, acc);
            }
            g_Y[(size_t)m*320 + p] = acc;
        }
    }
}

// ---------------- final linear: [8192,320] @ [320,256] + bl (128x64 tiles) ----------------
__global__ void __launch_bounds__(256) gemm_kernel(const float* __restrict__ wl,
                                                   const float* __restrict__ bl,
                                                   float* __restrict__ out){
    __shared__ float As[16*132];
    __shared__ __align__(16) float Bs[16*64];
    int t  = threadIdx.x;
    int bm = blockIdx.x*128, bn = blockIdx.y*64;
    int tx = t & 15, ty = t >> 4;
    float acc[8][4];
    #pragma unroll
    for (int i = 0; i < 8; i++)
        #pragma unroll
        for (int j = 0; j < 4; j++) acc[i][j] = 0.f;

    for (int k0 = 0; k0 < 320; k0 += 16){
        #pragma unroll
        for (int i = 0; i < 2; i++){
            int item = t + 256*i;
            int r = item >> 2, c4 = item & 3;
            float4 v = *(const float4*)&g_Y[(size_t)(bm + r)*320 + k0 + c4*4];
            As[(c4*4+0)*132 + r] = v.x;
            As[(c4*4+1)*132 + r] = v.y;
            As[(c4*4+2)*132 + r] = v.z;
            As[(c4*4+3)*132 + r] = v.w;
        }
        {
            int r = t >> 4, c = (t & 15)*4;
            float4 v = *(const float4*)&wl[(size_t)(k0 + r)*256 + bn + c];
            *(float4*)&Bs[r*64 + c] = v;
        }
        __syncthreads();
        #pragma unroll
        for (int kk = 0; kk < 16; kk++){
            float a[8], b[4];
            #pragma unroll
            for (int i = 0; i < 8; i++) a[i] = As[kk*132 + ty*8 + i];
            #pragma unroll
            for (int j = 0; j < 4; j++) b[j] = Bs[kk*64 + tx*4 + j];
            #pragma unroll
            for (int i = 0; i < 8; i++)
                #pragma unroll
                for (int j = 0; j < 4; j++) acc[i][j] = fmaf(a[i], b[j], acc[i][j]);
        }
        __syncthreads();
    }
    #pragma unroll
    for (int i = 0; i < 8; i++){
        int row = bm + ty*8 + i;
        #pragma unroll
        for (int j = 0; j < 4; j++){
            int col = bn + tx*4 + j;
            out[(size_t)row*256 + col] = acc[i][j] + __ldg(&bl[col]);
        }
    }
}

// ---------------- launch: fork/join overlap of independent chains ----------------
extern "C" void kernel_launch(void* const* d_in, const int* in_sizes, int n_in,
                              void* d_out, int out_size){
    const float* x    = (const float*)d_in[0];
    const float* pos  = (const float*)d_in[1];
    const float* w1a  = (const float*)d_in[2];
    const float* b1a  = (const float*)d_in[3];
    const float* g1a  = (const float*)d_in[4];
    const float* be1a = (const float*)d_in[5];
    const float* w1b  = (const float*)d_in[6];
    const float* b1b  = (const float*)d_in[7];
    const float* g1b  = (const float*)d_in[8];
    const float* be1b = (const float*)d_in[9];
    const float* w2   = (const float*)d_in[10];
    const float* b2   = (const float*)d_in[11];
    const float* g2a  = (const float*)d_in[12];
    const float* be2a = (const float*)d_in[13];
    const float* wc2a = (const float*)d_in[14];
    const float* bc2a = (const float*)d_in[15];
    const float* g2b  = (const float*)d_in[16];
    const float* be2b = (const float*)d_in[17];
    const float* wc2b = (const float*)d_in[18];
    const float* bc2b = (const float*)d_in[19];
    const float* g2c  = (const float*)d_in[20];
    const float* be2c = (const float*)d_in[21];
    const float* wcd  = (const float*)d_in[22];
    const float* bcd  = (const float*)d_in[23];
    const float* wl   = (const float*)d_in[24];
    const float* bl   = (const float*)d_in[25];
    float* out = (float*)d_out;

    // side stream + fork/join events (host-side objects only)
    cudaStream_t s2;
    cudaStreamCreateWithFlags(&s2, cudaStreamNonBlocking);
    cudaEvent_t eFork, eJoin;
    cudaEventCreateWithFlags(&eFork, cudaEventDisableTiming);
    cudaEventCreateWithFlags(&eJoin, cudaEventDisableTiming);

    pack_pos_kernel<<<32, 256>>>(pos);
    knn_kernel<<<2048, 128>>>();

    // fork: chain B (mlp2a -> gconv0 -> gconv1) uses psumD/psumB only
    cudaEventRecord(eFork, 0);
    cudaStreamWaitEvent(s2, eFork, 0);
    mlp2a_kernel<<<128, 256, 0, s2>>>(w2, b2);
    gconv_kernel<0, true><<<512, 256, 0, s2>>>(wc2a, bc2a, g2a, be2a);
    gconv_kernel<1, false><<<512, 256, 0, s2>>>(wc2b, bc2b, g2b, be2b);
    cudaEventRecord(eJoin, s2);

    // chain A on the main stream uses psum (S1) + psumC (S2)
    mlp1a_kernel<<<512, 256>>>(w1a, b1a);
    bn_phase2_kernel<<<32, 32>>>(512, 32, MK, g1a, be1a, OFF_S1);
    mlp1b_kernel<<<512, 256>>>(w1a, b1a, w1b, b1b);

    // join: bn_final needs psumC (chain A) + psumD (chain B)
    cudaStreamWaitEvent(0, eJoin, 0);
    bn_final_kernel<<<288, 32>>>(g1b, be1b, g2c, be2c);
    xconv_kernel<<<MPTS, 128>>>(x, wcd, bcd);
    gemm_kernel<<<dim3(64, 4), 256>>>(wl, bl, out);
}